// round 4
// baseline (speedup 1.0000x reference)
#include <cuda_runtime.h>
#include <math.h>

// ---------------- problem constants ----------------
constexpr int B_ = 16, N_ = 3136, C_ = 512, H_ = 8, D_ = 64;
constexpr int HH = 56, POOL = 12, AG = 144;
constexpr long M_ = (long)B_ * N_;                 // 50176
constexpr long QKV_ELEMS = M_ * 3 * C_;            // 77,070,336
constexpr long AGENT_ELEMS = (long)B_ * AG * C_;   // 1,179,648
constexpr long S_ELEMS = (long)B_ * H_ * AG * N_;  // 57,802,752
constexpr long AV_ELEMS = (long)B_ * H_ * AG * D_; // 1,179,648
constexpr long Y_ELEMS = M_ * C_;                  // 25,690,112

// ---------------- scratch (static device globals; no allocations) ----------------
__device__ float g_qkv[QKV_ELEMS];
__device__ float g_agent[AGENT_ELEMS];
__device__ float g_S[S_ELEMS];     // reused: stage1 logits (z,144,3136) then stage2 logits (z,3136,144)
__device__ float g_av[AV_ELEMS];
__device__ float g_y[Y_ELEMS];

// ---------------- generic batched SGEMM ----------------
// C[m,n] = alpha * sum_k A[m,k] * B(n,k)   (+ bias[n])
// A is row-major [M x K] with leading dim lda (k contiguous).
// BKN=false: B is [N x K], k contiguous, leading dim ldb.
// BKN=true : B is [K x N], n contiguous, leading dim ldb.
// Batch (blockIdx.z): offset = (z/8)*Out + (z%8)*In per operand.
template<int BM, int BN, int BK, int TM, int TN, bool BKN>
__global__ __launch_bounds__((BM / TM) * (BN / TN))
void gemm_kernel(const float* __restrict__ A, const float* __restrict__ B,
                 float* __restrict__ C,
                 int M, int N, int K, int lda, int ldb, int ldc,
                 long aOut, long aIn, long bOut, long bIn, long cOut, long cIn,
                 float alpha, const float* __restrict__ bias)
{
    const int z = blockIdx.z;
    A += (long)(z >> 3) * aOut + (long)(z & 7) * aIn;
    B += (long)(z >> 3) * bOut + (long)(z & 7) * bIn;
    C += (long)(z >> 3) * cOut + (long)(z & 7) * cIn;

    __shared__ float As[BK][BM];
    __shared__ float Bs[BK][BN];

    const int tid = threadIdx.x;
    const int m0 = blockIdx.y * BM;
    const int n0 = blockIdx.x * BN;
    const int tr = tid / (BN / TN);
    const int tc = tid % (BN / TN);

    float acc[TM][TN];
#pragma unroll
    for (int i = 0; i < TM; i++)
#pragma unroll
        for (int j = 0; j < TN; j++) acc[i][j] = 0.f;

    const int aR = tid / (BK / 4);
    const int aK = (tid % (BK / 4)) * 4;
    int bR, bK;
    if (BKN) { bR = tid / (BN / 4); bK = (tid % (BN / 4)) * 4; }
    else     { bR = tid / (BK / 4); bK = (tid % (BK / 4)) * 4; }

    for (int k0 = 0; k0 < K; k0 += BK) {
        float4 av4 = make_float4(0.f, 0.f, 0.f, 0.f);
        if (m0 + aR < M)
            av4 = *(const float4*)(A + (long)(m0 + aR) * lda + k0 + aK);
        As[aK + 0][aR] = av4.x; As[aK + 1][aR] = av4.y;
        As[aK + 2][aR] = av4.z; As[aK + 3][aR] = av4.w;

        if (BKN) {
            float4 bv = make_float4(0.f, 0.f, 0.f, 0.f);
            if (n0 + bK < N)
                bv = *(const float4*)(B + (long)(k0 + bR) * ldb + n0 + bK);
            *(float4*)&Bs[bR][bK] = bv;
        } else {
            float4 bv = make_float4(0.f, 0.f, 0.f, 0.f);
            if (n0 + bR < N)
                bv = *(const float4*)(B + (long)(n0 + bR) * ldb + k0 + bK);
            Bs[bK + 0][bR] = bv.x; Bs[bK + 1][bR] = bv.y;
            Bs[bK + 2][bR] = bv.z; Bs[bK + 3][bR] = bv.w;
        }
        __syncthreads();

#pragma unroll
        for (int kk = 0; kk < BK; kk++) {
            float ra[TM], rb[TN];
#pragma unroll
            for (int i = 0; i < TM; i++) ra[i] = As[kk][tr * TM + i];
#pragma unroll
            for (int j = 0; j < TN; j++) rb[j] = Bs[kk][tc * TN + j];
#pragma unroll
            for (int i = 0; i < TM; i++)
#pragma unroll
                for (int j = 0; j < TN; j++)
                    acc[i][j] = fmaf(ra[i], rb[j], acc[i][j]);
        }
        __syncthreads();
    }

#pragma unroll
    for (int i = 0; i < TM; i++) {
        int gm = m0 + tr * TM + i;
        if (gm >= M) continue;
#pragma unroll
        for (int j = 0; j < TN; j++) {
            int gn = n0 + tc * TN + j;
            if (gn >= N) continue;
            float v = alpha * acc[i][j];
            if (bias) v += bias[gn];
            C[(long)gm * ldc + gn] = v;
        }
    }
}

// ---------------- adaptive avg pool of q -> agent tokens ----------------
__global__ void pool_kernel(const float* __restrict__ qkv, float* __restrict__ agent)
{
    int b = blockIdx.x;
    int pq = blockIdx.y;               // 0..143
    int p = pq / POOL, q = pq % POOL;
    int ch = threadIdx.x;              // 0..511  (q occupies first 512 channels)
    int hs = (p * HH) / POOL, he = ((p + 1) * HH + POOL - 1) / POOL;
    int ws = (q * HH) / POOL, we = ((q + 1) * HH + POOL - 1) / POOL;
    float inv = 1.0f / (float)((he - hs) * (we - ws));
    const float* base = qkv + (long)b * N_ * 1536;
    float s = 0.f;
    for (int h = hs; h < he; h++)
        for (int w = ws; w < we; w++)
            s += base[(long)(h * HH + w) * 1536 + ch];
    agent[((long)b * AG + pq) * C_ + ch] = s * inv;
}

// ---------------- softmax over rows of length rowLen (block per row) ----------------
__global__ void softmax_rows(float* __restrict__ S, int rowLen)
{
    float* row = S + (long)blockIdx.x * rowLen;
    const int tid = threadIdx.x;
    __shared__ float sm[8];
    __shared__ float bcast;

    float m = -3.4e38f;
    for (int i = tid; i < rowLen; i += 256) m = fmaxf(m, row[i]);
#pragma unroll
    for (int o = 16; o; o >>= 1) m = fmaxf(m, __shfl_xor_sync(0xffffffffu, m, o));
    if ((tid & 31) == 0) sm[tid >> 5] = m;
    __syncthreads();
    if (tid == 0) {
        float v = sm[0];
        for (int i = 1; i < 8; i++) v = fmaxf(v, sm[i]);
        bcast = v;
    }
    __syncthreads();
    m = bcast;

    float s = 0.f;
    for (int i = tid; i < rowLen; i += 256) {
        float e = __expf(row[i] - m);
        row[i] = e;
        s += e;
    }
#pragma unroll
    for (int o = 16; o; o >>= 1) s += __shfl_xor_sync(0xffffffffu, s, o);
    __syncthreads();
    if ((tid & 31) == 0) sm[tid >> 5] = s;
    __syncthreads();
    if (tid == 0) {
        float v = 0.f;
        for (int i = 0; i < 8; i++) v += sm[i];
        bcast = 1.0f / v;
    }
    __syncthreads();
    float inv = bcast;
    for (int i = tid; i < rowLen; i += 256) row[i] *= inv;
}

// ---------------- softmax over rows of length 144 (warp per row) ----------------
__global__ void softmax_small(float* __restrict__ S, long nrows)
{
    long gw = ((long)blockIdx.x * blockDim.x + threadIdx.x) >> 5;
    if (gw >= nrows) return;
    int lane = threadIdx.x & 31;
    float* row = S + gw * 144;
    float v[5];
    float m = -3.4e38f;
#pragma unroll
    for (int j = 0; j < 5; j++) {
        int i = lane + j * 32;
        v[j] = (i < 144) ? row[i] : -3.4e38f;
        m = fmaxf(m, v[j]);
    }
#pragma unroll
    for (int o = 16; o; o >>= 1) m = fmaxf(m, __shfl_xor_sync(0xffffffffu, m, o));
    float s = 0.f;
#pragma unroll
    for (int j = 0; j < 5; j++) {
        int i = lane + j * 32;
        if (i < 144) { v[j] = __expf(v[j] - m); s += v[j]; }
    }
#pragma unroll
    for (int o = 16; o; o >>= 1) s += __shfl_xor_sync(0xffffffffu, s, o);
    float inv = 1.0f / s;
#pragma unroll
    for (int j = 0; j < 5; j++) {
        int i = lane + j * 32;
        if (i < 144) row[i] = v[j] * inv;
    }
}

// ---------------- depthwise 3x3 conv on v + bias, residual add into y ----------------
__global__ void dwc_add(const float* __restrict__ qkv, const float* __restrict__ w,
                        const float* __restrict__ bias, float* __restrict__ y)
{
    long idx = (long)blockIdx.x * blockDim.x + threadIdx.x;
    if (idx >= Y_ELEMS) return;
    int ch = (int)(idx & (C_ - 1));
    long t = idx >> 9;
    int l = (int)(t % N_);
    int b = (int)(t / N_);
    int hh = l / HH, ww = l % HH;
    const float* vbase = qkv + (long)b * N_ * 1536 + 1024 + ch;
    float s = bias[ch];
#pragma unroll
    for (int kh = 0; kh < 3; kh++) {
        int h2 = hh + kh - 1;
        if (h2 < 0 || h2 >= HH) continue;
#pragma unroll
        for (int kw = 0; kw < 3; kw++) {
            int w2 = ww + kw - 1;
            if (w2 < 0 || w2 >= HH) continue;
            s = fmaf(vbase[(long)(h2 * HH + w2) * 1536], w[ch * 9 + kh * 3 + kw], s);
        }
    }
    y[idx] += s;
}

// ---------------- launch ----------------
extern "C" void kernel_launch(void* const* d_in, const int* in_sizes, int n_in,
                              void* d_out, int out_size)
{
    const float* x      = (const float*)d_in[0];
    const float* qkv_w  = (const float*)d_in[1];
    const float* proj_w = (const float*)d_in[2];
    const float* proj_b = (const float*)d_in[3];
    const float* dwc_w  = (const float*)d_in[4];
    const float* dwc_b  = (const float*)d_in[5];
    float* out = (float*)d_out;

    float *qkv, *agent, *S, *av, *y;
    cudaGetSymbolAddress((void**)&qkv,   g_qkv);
    cudaGetSymbolAddress((void**)&agent, g_agent);
    cudaGetSymbolAddress((void**)&S,     g_S);
    cudaGetSymbolAddress((void**)&av,    g_av);
    cudaGetSymbolAddress((void**)&y,     g_y);

    const long BQKV = (long)N_ * 1536;        // per-batch stride in qkv buffer (4,816,896)
    const float scale = 0.125f;               // d^-0.5, d=64

    // 1) qkv = x @ qkv_w^T : [50176 x 1536]
    gemm_kernel<128, 128, 8, 8, 8, false><<<dim3(12, 392, 1), 256>>>(
        x, qkv_w, qkv, 50176, 1536, 512, 512, 512, 1536,
        0, 0, 0, 0, 0, 0, 1.f, nullptr);

    // 2) agent tokens = adaptive 12x12 pool of q
    pool_kernel<<<dim3(B_, AG), 512>>>(qkv, agent);

    // 3) stage-1 logits: S[z,p,l] = scale * ah @ kh^T   (z = b*8 + h)
    gemm_kernel<64, 64, 16, 4, 4, false><<<dim3(49, 3, 128), 256>>>(
        agent, qkv + 512, S, AG, N_, 64, 512, 1536, N_,
        (long)AG * C_, 64, BQKV, 64, 8L * AG * N_, (long)AG * N_,
        scale, nullptr);

    // 4) softmax over l (rows of 3136)
    softmax_rows<<<B_ * H_ * AG, 256>>>(S, N_);

    // 5) agent_v[z,p,d] = S @ vh
    gemm_kernel<64, 64, 16, 4, 4, true><<<dim3(1, 3, 128), 256>>>(
        S, qkv + 1024, av, AG, 64, N_, N_, 1536, 64,
        8L * AG * N_, (long)AG * N_, BQKV, 64, 8L * AG * 64, (long)AG * 64,
        1.f, nullptr);

    // 6) stage-2 logits: S[z,l,p] = scale * qh @ ah^T
    gemm_kernel<64, 64, 16, 4, 4, false><<<dim3(3, 49, 128), 256>>>(
        qkv, agent, S, N_, AG, 64, 1536, 512, AG,
        BQKV, 64, (long)AG * C_, 64, 8L * N_ * AG, (long)N_ * AG,
        scale, nullptr);

    // 7) softmax over p (rows of 144)
    {
        long nrows = (long)B_ * H_ * N_;   // 401408
        int blocks = (int)((nrows * 32 + 255) / 256);
        softmax_small<<<blocks, 256>>>(S, nrows);
    }

    // 8) y[b,l,h*64+d] = S @ agent_v
    gemm_kernel<64, 64, 16, 4, 4, true><<<dim3(1, 49, 128), 256>>>(
        S, av, y, N_, 64, AG, AG, 64, C_,
        8L * N_ * AG, (long)N_ * AG, 8L * AG * 64, (long)AG * 64,
        (long)N_ * C_, 64, 1.f, nullptr);

    // 9) y += depthwise3x3(v) + dwc_b
    {
        int blocks = (int)((Y_ELEMS + 255) / 256);
        dwc_add<<<blocks, 256>>>(qkv, dwc_w, dwc_b, y);
    }

    // 10) out = y @ proj_w^T + proj_b
    gemm_kernel<128, 128, 8, 8, 8, false><<<dim3(4, 392, 1), 256>>>(
        y, proj_w, out, 50176, 512, 512, 512, 512, 512,
        0, 0, 0, 0, 0, 0, 1.f, proj_b);
}

// round 7
// speedup vs baseline: 1.8982x; 1.8982x over previous
#include <cuda_runtime.h>
#include <cstdint>
#include <math.h>

// ---------------- problem constants ----------------
constexpr int B_ = 16, N_ = 3136, C_ = 512, H_ = 8, D_ = 64;
constexpr int HH = 56, POOL = 12, AG = 144;
constexpr long M_ = (long)B_ * N_;                 // 50176
constexpr long QKV_ELEMS = M_ * 3 * C_;            // 77,070,336
constexpr long AGENT_ELEMS = (long)B_ * AG * C_;   // 1,179,648
constexpr long S_ELEMS = (long)B_ * H_ * AG * N_;  // 57,802,752
constexpr long AV_ELEMS = (long)B_ * H_ * AG * D_; // 1,179,648
constexpr long Y_ELEMS = M_ * C_;                  // 25,690,112

// ---------------- scratch (static device globals; no allocations) ----------------
__device__ float g_qkv[QKV_ELEMS];
__device__ float g_agent[AGENT_ELEMS];
__device__ float g_S[S_ELEMS];
__device__ float g_av[AV_ELEMS];
__device__ float g_y[Y_ELEMS];
__device__ float g_wr[786432];   // rounded weights (qkv_w 786432; proj_w 262144 fits)

// ================= small helpers =================
__device__ __forceinline__ uint32_t smem_u32(const void* p) {
    uint32_t a;
    asm("{ .reg .u64 t; cvta.to.shared.u64 t, %1; cvt.u32.u64 %0, t; }" : "=r"(a) : "l"(p));
    return a;
}
__device__ __forceinline__ float tf32r(float f) {
    uint32_t r;
    asm("cvt.rna.tf32.f32 %0, %1;" : "=r"(r) : "f"(f));
    return __uint_as_float(r);
}
__device__ __forceinline__ void cpa16(uint32_t dst, const float* src) {
    asm volatile("cp.async.cg.shared.global [%0], [%1], 16;" :: "r"(dst), "l"(src));
}
#define CP_COMMIT() asm volatile("cp.async.commit_group;" ::: "memory")
template<int N> __device__ __forceinline__ void cp_wait() {
    asm volatile("cp.async.wait_group %0;" :: "n"(N) : "memory");
}
__device__ __forceinline__ void mma_tf32(float* c, const uint32_t* a, const uint32_t* b) {
    asm volatile(
        "mma.sync.aligned.m16n8k8.row.col.f32.tf32.tf32.f32 "
        "{%0,%1,%2,%3}, {%4,%5,%6,%7}, {%8,%9}, {%0,%1,%2,%3};"
        : "+f"(c[0]), "+f"(c[1]), "+f"(c[2]), "+f"(c[3])
        : "r"(a[0]), "r"(a[1]), "r"(a[2]), "r"(a[3]), "r"(b[0]), "r"(b[1]));
}

// ---------------- tf32 rounding pre-pass (float4 granularity) ----------------
__global__ void round_copy(const float* __restrict__ in, float* __restrict__ out, long n4)
{
    long i = (long)blockIdx.x * blockDim.x + threadIdx.x;
    if (i >= n4) return;
    float4 v = ((const float4*)in)[i];
    v.x = tf32r(v.x); v.y = tf32r(v.y); v.z = tf32r(v.z); v.w = tf32r(v.w);
    ((float4*)out)[i] = v;
}

// ================= tensor-core (mma.sync tf32) GEMM =================
// C[m,n] = sum_k A[m,k]*B[n,k] (+bias[n]).  Exact tiles: M%128==0, N%128==0, K%32==0.
// Inputs must already be tf32-rounded.
constexpr int PADW = 36;                 // floats per smem row (bank-conflict-free, 16B aligned)
constexpr int STG  = 128 * PADW;         // floats per operand per stage (4608)
constexpr int GEMM_SMEM = 4 * STG * 4;   // 73,728 bytes

__global__ __launch_bounds__(256, 2)
void gemm_mma(const float* __restrict__ A, const float* __restrict__ Bw, float* __restrict__ C,
              int K, int lda, int ldb, int ldc, const float* __restrict__ bias)
{
    extern __shared__ float smem[];      // [stage0: A,B][stage1: A,B]
    const int tid = threadIdx.x;
    const int wid = tid >> 5, lane = tid & 31;
    const int wm = wid >> 2, wn = wid & 3;           // 2 x 4 warp grid
    const long m0 = (long)blockIdx.y * 128;
    const long n0 = (long)blockIdx.x * 128;

    // cp.async slot mapping: thread -> (row = tid/8 + 32i, 16B seg = tid%8)
    const int r  = tid >> 3;
    const int c4 = (tid & 7) << 2;
    const uint32_t sbase = smem_u32(smem);
    const uint32_t aAddr0 = sbase + (uint32_t)((r * PADW + c4) * 4);
    const uint32_t bAddr0 = aAddr0 + (uint32_t)(STG * 4);
    const float* aSrc = A + (m0 + r) * (long)lda + c4;
    const float* bSrc = Bw + (n0 + r) * (long)ldb + c4;

    // fragment base pointers
    const int g = lane >> 2, t4 = lane & 3;
    const float* aF0 = smem + (wm * 64 + g) * PADW + t4;
    const float* bF0 = smem + STG + (wn * 32 + g) * PADW + t4;

    float acc[4][4][4];
#pragma unroll
    for (int i = 0; i < 4; i++)
#pragma unroll
        for (int j = 0; j < 4; j++)
#pragma unroll
            for (int l = 0; l < 4; l++) acc[i][j][l] = 0.f;

    const int nch = K / 32;

    auto issue = [&](int s, int c) {
        const uint32_t so = (uint32_t)(s * 2 * STG * 4);
        const long ko = (long)c * 32;
#pragma unroll
        for (int i = 0; i < 4; i++) {
            cpa16(aAddr0 + so + (uint32_t)(i * 32 * PADW * 4), aSrc + (long)(32 * i) * lda + ko);
            cpa16(bAddr0 + so + (uint32_t)(i * 32 * PADW * 4), bSrc + (long)(32 * i) * ldb + ko);
        }
        CP_COMMIT();
    };

    issue(0, 0);
    issue(1, 1);

    for (int c = 0; c < nch; c++) {
        if (c + 1 < nch) cp_wait<1>(); else cp_wait<0>();
        __syncthreads();

        const int s = c & 1;
        const float* Af = aF0 + s * 2 * STG;
        const float* Bf = bF0 + s * 2 * STG;
#pragma unroll
        for (int ks = 0; ks < 4; ks++) {
            uint32_t a[4][4], b[4][2];
#pragma unroll
            for (int mt = 0; mt < 4; mt++) {
                const float* p = Af + mt * 16 * PADW + ks * 8;
                a[mt][0] = __float_as_uint(p[0]);
                a[mt][1] = __float_as_uint(p[8 * PADW]);
                a[mt][2] = __float_as_uint(p[4]);
                a[mt][3] = __float_as_uint(p[8 * PADW + 4]);
            }
#pragma unroll
            for (int nt = 0; nt < 4; nt++) {
                const float* p = Bf + nt * 8 * PADW + ks * 8;
                b[nt][0] = __float_as_uint(p[0]);
                b[nt][1] = __float_as_uint(p[4]);
            }
#pragma unroll
            for (int mt = 0; mt < 4; mt++)
#pragma unroll
                for (int nt = 0; nt < 4; nt++)
                    mma_tf32(acc[mt][nt], a[mt], b[nt]);
        }
        __syncthreads();
        if (c + 2 < nch) issue(s, c + 2);
    }

    // epilogue
    const long rowBase = m0 + wm * 64 + g;
#pragma unroll
    for (int mt = 0; mt < 4; mt++) {
        const long r0 = rowBase + mt * 16;
#pragma unroll
        for (int nt = 0; nt < 4; nt++) {
            const long col = n0 + wn * 32 + nt * 8 + t4 * 2;
            float2 v0 = make_float2(acc[mt][nt][0], acc[mt][nt][1]);
            float2 v1 = make_float2(acc[mt][nt][2], acc[mt][nt][3]);
            if (bias) {
                float2 bb = *(const float2*)&bias[col];
                v0.x += bb.x; v0.y += bb.y;
                v1.x += bb.x; v1.y += bb.y;
            }
            *(float2*)&C[r0 * (long)ldc + col] = v0;
            *(float2*)&C[(r0 + 8) * (long)ldc + col] = v1;
        }
    }
}

// ---------------- generic batched SGEMM (attention stages) ----------------
template<int BM, int BN, int BK, int TM, int TN, bool BKN>
__global__ __launch_bounds__((BM / TM) * (BN / TN))
void gemm_kernel(const float* __restrict__ A, const float* __restrict__ B,
                 float* __restrict__ C,
                 int M, int N, int K, int lda, int ldb, int ldc,
                 long aOut, long aIn, long bOut, long bIn, long cOut, long cIn,
                 float alpha, const float* __restrict__ bias)
{
    const int z = blockIdx.z;
    A += (long)(z >> 3) * aOut + (long)(z & 7) * aIn;
    B += (long)(z >> 3) * bOut + (long)(z & 7) * bIn;
    C += (long)(z >> 3) * cOut + (long)(z & 7) * cIn;

    __shared__ float As[BK][BM];
    __shared__ float Bs[BK][BN];

    const int tid = threadIdx.x;
    const int m0 = blockIdx.y * BM;
    const int n0 = blockIdx.x * BN;
    const int tr = tid / (BN / TN);
    const int tc = tid % (BN / TN);

    float acc[TM][TN];
#pragma unroll
    for (int i = 0; i < TM; i++)
#pragma unroll
        for (int j = 0; j < TN; j++) acc[i][j] = 0.f;

    const int aR = tid / (BK / 4);
    const int aK = (tid % (BK / 4)) * 4;
    int bR, bK;
    if (BKN) { bR = tid / (BN / 4); bK = (tid % (BN / 4)) * 4; }
    else     { bR = tid / (BK / 4); bK = (tid % (BK / 4)) * 4; }

    for (int k0 = 0; k0 < K; k0 += BK) {
        float4 av4 = make_float4(0.f, 0.f, 0.f, 0.f);
        if (m0 + aR < M)
            av4 = *(const float4*)(A + (long)(m0 + aR) * lda + k0 + aK);
        As[aK + 0][aR] = av4.x; As[aK + 1][aR] = av4.y;
        As[aK + 2][aR] = av4.z; As[aK + 3][aR] = av4.w;

        if (BKN) {
            float4 bv = make_float4(0.f, 0.f, 0.f, 0.f);
            if (n0 + bK < N)
                bv = *(const float4*)(B + (long)(k0 + bR) * ldb + n0 + bK);
            *(float4*)&Bs[bR][bK] = bv;
        } else {
            float4 bv = make_float4(0.f, 0.f, 0.f, 0.f);
            if (n0 + bR < N)
                bv = *(const float4*)(B + (long)(n0 + bR) * ldb + k0 + bK);
            Bs[bK + 0][bR] = bv.x; Bs[bK + 1][bR] = bv.y;
            Bs[bK + 2][bR] = bv.z; Bs[bK + 3][bR] = bv.w;
        }
        __syncthreads();

#pragma unroll
        for (int kk = 0; kk < BK; kk++) {
            float ra[TM], rb[TN];
#pragma unroll
            for (int i = 0; i < TM; i++) ra[i] = As[kk][tr * TM + i];
#pragma unroll
            for (int j = 0; j < TN; j++) rb[j] = Bs[kk][tc * TN + j];
#pragma unroll
            for (int i = 0; i < TM; i++)
#pragma unroll
                for (int j = 0; j < TN; j++)
                    acc[i][j] = fmaf(ra[i], rb[j], acc[i][j]);
        }
        __syncthreads();
    }

#pragma unroll
    for (int i = 0; i < TM; i++) {
        int gm = m0 + tr * TM + i;
        if (gm >= M) continue;
#pragma unroll
        for (int j = 0; j < TN; j++) {
            int gn = n0 + tc * TN + j;
            if (gn >= N) continue;
            float v = alpha * acc[i][j];
            if (bias) v += bias[gn];
            C[(long)gm * ldc + gn] = v;
        }
    }
}

// ---------------- adaptive avg pool of q -> agent tokens ----------------
__global__ void pool_kernel(const float* __restrict__ qkv, float* __restrict__ agent)
{
    int b = blockIdx.x;
    int pq = blockIdx.y;
    int p = pq / POOL, q = pq % POOL;
    int ch = threadIdx.x;
    int hs = (p * HH) / POOL, he = ((p + 1) * HH + POOL - 1) / POOL;
    int ws = (q * HH) / POOL, we = ((q + 1) * HH + POOL - 1) / POOL;
    float inv = 1.0f / (float)((he - hs) * (we - ws));
    const float* base = qkv + (long)b * N_ * 1536;
    float s = 0.f;
    for (int h = hs; h < he; h++)
        for (int w = ws; w < we; w++)
            s += base[(long)(h * HH + w) * 1536 + ch];
    agent[((long)b * AG + pq) * C_ + ch] = s * inv;
}

// ---------------- softmax over rows of length rowLen (block per row) ----------------
__global__ void softmax_rows(float* __restrict__ S, int rowLen)
{
    float* row = S + (long)blockIdx.x * rowLen;
    const int tid = threadIdx.x;
    __shared__ float sm[8];
    __shared__ float bcast;

    float m = -3.4e38f;
    for (int i = tid; i < rowLen; i += 256) m = fmaxf(m, row[i]);
#pragma unroll
    for (int o = 16; o; o >>= 1) m = fmaxf(m, __shfl_xor_sync(0xffffffffu, m, o));
    if ((tid & 31) == 0) sm[tid >> 5] = m;
    __syncthreads();
    if (tid == 0) {
        float v = sm[0];
        for (int i = 1; i < 8; i++) v = fmaxf(v, sm[i]);
        bcast = v;
    }
    __syncthreads();
    m = bcast;

    float s = 0.f;
    for (int i = tid; i < rowLen; i += 256) {
        float e = __expf(row[i] - m);
        row[i] = e;
        s += e;
    }
#pragma unroll
    for (int o = 16; o; o >>= 1) s += __shfl_xor_sync(0xffffffffu, s, o);
    __syncthreads();
    if ((tid & 31) == 0) sm[tid >> 5] = s;
    __syncthreads();
    if (tid == 0) {
        float v = 0.f;
        for (int i = 0; i < 8; i++) v += sm[i];
        bcast = 1.0f / v;
    }
    __syncthreads();
    float inv = bcast;
    for (int i = tid; i < rowLen; i += 256) row[i] *= inv;
}

// ---------------- softmax over rows of length 144 (warp per row) ----------------
__global__ void softmax_small(float* __restrict__ S, long nrows)
{
    long gw = ((long)blockIdx.x * blockDim.x + threadIdx.x) >> 5;
    if (gw >= nrows) return;
    int lane = threadIdx.x & 31;
    float* row = S + gw * 144;
    float v[5];
    float m = -3.4e38f;
#pragma unroll
    for (int j = 0; j < 5; j++) {
        int i = lane + j * 32;
        v[j] = (i < 144) ? row[i] : -3.4e38f;
        m = fmaxf(m, v[j]);
    }
#pragma unroll
    for (int o = 16; o; o >>= 1) m = fmaxf(m, __shfl_xor_sync(0xffffffffu, m, o));
    float s = 0.f;
#pragma unroll
    for (int j = 0; j < 5; j++) {
        int i = lane + j * 32;
        if (i < 144) { v[j] = __expf(v[j] - m); s += v[j]; }
    }
#pragma unroll
    for (int o = 16; o; o >>= 1) s += __shfl_xor_sync(0xffffffffu, s, o);
    float inv = 1.0f / s;
#pragma unroll
    for (int j = 0; j < 5; j++) {
        int i = lane + j * 32;
        if (i < 144) row[i] = v[j] * inv;
    }
}

// ---------------- depthwise 3x3 conv on v + bias, residual add into y ----------------
__global__ void dwc_add(const float* __restrict__ qkv, const float* __restrict__ w,
                        const float* __restrict__ bias, float* __restrict__ y)
{
    long idx = (long)blockIdx.x * blockDim.x + threadIdx.x;
    if (idx >= Y_ELEMS) return;
    int ch = (int)(idx & (C_ - 1));
    long t = idx >> 9;
    int l = (int)(t % N_);
    int b = (int)(t / N_);
    int hh = l / HH, ww = l % HH;
    const float* vbase = qkv + (long)b * N_ * 1536 + 1024 + ch;
    float s = bias[ch];
#pragma unroll
    for (int kh = 0; kh < 3; kh++) {
        int h2 = hh + kh - 1;
        if (h2 < 0 || h2 >= HH) continue;
#pragma unroll
        for (int kw = 0; kw < 3; kw++) {
            int w2 = ww + kw - 1;
            if (w2 < 0 || w2 >= HH) continue;
            s = fmaf(vbase[(long)(h2 * HH + w2) * 1536], w[ch * 9 + kh * 3 + kw], s);
        }
    }
    y[idx] += s;
}

// ---------------- launch ----------------
extern "C" void kernel_launch(void* const* d_in, const int* in_sizes, int n_in,
                              void* d_out, int out_size)
{
    const float* x      = (const float*)d_in[0];
    const float* qkv_w  = (const float*)d_in[1];
    const float* proj_w = (const float*)d_in[2];
    const float* proj_b = (const float*)d_in[3];
    const float* dwc_w  = (const float*)d_in[4];
    const float* dwc_b  = (const float*)d_in[5];
    float* out = (float*)d_out;

    float *qkv, *agent, *S, *av, *y, *wr;
    cudaGetSymbolAddress((void**)&qkv,   g_qkv);
    cudaGetSymbolAddress((void**)&agent, g_agent);
    cudaGetSymbolAddress((void**)&S,     g_S);
    cudaGetSymbolAddress((void**)&av,    g_av);
    cudaGetSymbolAddress((void**)&y,     g_y);
    cudaGetSymbolAddress((void**)&wr,    g_wr);

    cudaFuncSetAttribute(gemm_mma, cudaFuncAttributeMaxDynamicSharedMemorySize, GEMM_SMEM);

    const long BQKV = (long)N_ * 1536;
    const float scale = 0.125f;

    // 0) tf32-round x (into y scratch, free until step 8) and qkv_w
    {
        long n4 = Y_ELEMS / 4;                     // 6,422,528
        round_copy<<<(int)((n4 + 255) / 256), 256>>>(x, y, n4);
        long w4 = 786432 / 4;
        round_copy<<<(int)((w4 + 255) / 256), 256>>>(qkv_w, wr, w4);
    }

    // 1) qkv = x @ qkv_w^T : [50176 x 1536]   (mma.sync tf32)
    gemm_mma<<<dim3(12, 392), 256, GEMM_SMEM>>>(y, wr, qkv, 512, 512, 512, 1536, nullptr);

    // 2) agent tokens = adaptive 12x12 pool of q
    pool_kernel<<<dim3(B_, AG), 512>>>(qkv, agent);

    // 3) stage-1 logits: S[z,p,l] = scale * ah @ kh^T
    gemm_kernel<64, 64, 16, 4, 4, false><<<dim3(49, 3, 128), 256>>>(
        agent, qkv + 512, S, AG, N_, 64, 512, 1536, N_,
        (long)AG * C_, 64, BQKV, 64, 8L * AG * N_, (long)AG * N_,
        scale, nullptr);

    // 4) softmax over l (rows of 3136)
    softmax_rows<<<B_ * H_ * AG, 256>>>(S, N_);

    // 5) agent_v[z,p,d] = S @ vh
    gemm_kernel<64, 64, 16, 4, 4, true><<<dim3(1, 3, 128), 256>>>(
        S, qkv + 1024, av, AG, 64, N_, N_, 1536, 64,
        8L * AG * N_, (long)AG * N_, BQKV, 64, 8L * AG * 64, (long)AG * 64,
        1.f, nullptr);

    // 6) stage-2 logits: S[z,l,p] = scale * qh @ ah^T
    gemm_kernel<64, 64, 16, 4, 4, false><<<dim3(3, 49, 128), 256>>>(
        qkv, agent, S, N_, AG, 64, 1536, 512, AG,
        BQKV, 64, (long)AG * C_, 64, 8L * N_ * AG, (long)N_ * AG,
        scale, nullptr);

    // 7) softmax over p (rows of 144)
    {
        long nrows = (long)B_ * H_ * N_;
        int blocks = (int)((nrows * 32 + 255) / 256);
        softmax_small<<<blocks, 256>>>(S, nrows);
    }

    // 8) y[b,l,h*64+d] = S @ agent_v
    gemm_kernel<64, 64, 16, 4, 4, true><<<dim3(1, 49, 128), 256>>>(
        S, av, y, N_, 64, AG, AG, 64, C_,
        8L * N_ * AG, (long)N_ * AG, 8L * AG * 64, (long)AG * 64,
        (long)N_ * C_, 64, 1.f, nullptr);

    // 9) y += depthwise3x3(v) + dwc_b
    {
        int blocks = (int)((Y_ELEMS + 255) / 256);
        dwc_add<<<blocks, 256>>>(qkv, dwc_w, dwc_b, y);
    }

    // 9.5) tf32-round y (in place) and proj_w
    {
        long n4 = Y_ELEMS / 4;
        round_copy<<<(int)((n4 + 255) / 256), 256>>>(y, y, n4);
        long w4 = 262144 / 4;
        round_copy<<<(int)((w4 + 255) / 256), 256>>>(proj_w, wr, w4);
    }

    // 10) out = y @ proj_w^T + proj_b   (mma.sync tf32)
    gemm_mma<<<dim3(4, 392), 256, GEMM_SMEM>>>(y, wr, out, 512, 512, 512, 512, proj_b);
}

// round 8
// speedup vs baseline: 2.5814x; 1.3599x over previous
#include <cuda_runtime.h>
#include <cstdint>
#include <math.h>

// ---------------- problem constants ----------------
constexpr int B_ = 16, N_ = 3136, C_ = 512, H_ = 8, D_ = 64;
constexpr int HH = 56, POOL = 12, AG = 144;
constexpr long M_ = (long)B_ * N_;                 // 50176
constexpr long QKV_ELEMS = M_ * 3 * C_;            // 77,070,336
constexpr long AGENT_ELEMS = (long)B_ * AG * C_;   // 1,179,648
constexpr long S_ELEMS = (long)B_ * H_ * AG * N_;  // 57,802,752
constexpr long AV_ELEMS = (long)B_ * H_ * AG * D_; // 1,179,648
constexpr long Y_ELEMS = M_ * C_;                  // 25,690,112

// ---------------- scratch (static device globals; no allocations) ----------------
__device__ float g_qkv[QKV_ELEMS];
__device__ float g_agent[AGENT_ELEMS];
__device__ float g_S[S_ELEMS];
__device__ float g_av[AV_ELEMS];
__device__ float g_y[Y_ELEMS];
__device__ float g_wr[786432];   // rounded weights (qkv_w 786432; proj_w 262144 fits)

// ================= small helpers =================
__device__ __forceinline__ uint32_t smem_u32(const void* p) {
    uint32_t a;
    asm("{ .reg .u64 t; cvta.to.shared.u64 t, %1; cvt.u32.u64 %0, t; }" : "=r"(a) : "l"(p));
    return a;
}
__device__ __forceinline__ float tf32r(float f) {
    uint32_t r;
    asm("cvt.rna.tf32.f32 %0, %1;" : "=r"(r) : "f"(f));
    return __uint_as_float(r);
}
__device__ __forceinline__ void cpa16(uint32_t dst, const float* src) {
    asm volatile("cp.async.cg.shared.global [%0], [%1], 16;" :: "r"(dst), "l"(src));
}
#define CP_COMMIT() asm volatile("cp.async.commit_group;" ::: "memory")
template<int N> __device__ __forceinline__ void cp_wait() {
    asm volatile("cp.async.wait_group %0;" :: "n"(N) : "memory");
}
__device__ __forceinline__ void mma_tf32(float* c, const uint32_t* a, const uint32_t* b) {
    asm volatile(
        "mma.sync.aligned.m16n8k8.row.col.f32.tf32.tf32.f32 "
        "{%0,%1,%2,%3}, {%4,%5,%6,%7}, {%8,%9}, {%0,%1,%2,%3};"
        : "+f"(c[0]), "+f"(c[1]), "+f"(c[2]), "+f"(c[3])
        : "r"(a[0]), "r"(a[1]), "r"(a[2]), "r"(a[3]), "r"(b[0]), "r"(b[1]));
}

// ---------------- tf32 rounding pre-pass (float4 granularity) ----------------
__global__ void round_copy(const float* __restrict__ in, float* __restrict__ out, long n4)
{
    long i = (long)blockIdx.x * blockDim.x + threadIdx.x;
    if (i >= n4) return;
    float4 v = ((const float4*)in)[i];
    v.x = tf32r(v.x); v.y = tf32r(v.y); v.z = tf32r(v.z); v.w = tf32r(v.w);
    ((float4*)out)[i] = v;
}

// ================= large tensor-core GEMM (qkv / proj) =================
// C[m,n] = sum_k A[m,k]*B[n,k] (+bias[n]).  Exact tiles: M%128==0, N%128==0, K%32==0.
// Inputs must already be tf32-rounded.
constexpr int PADW = 36;                 // floats per smem row
constexpr int STG  = 128 * PADW;         // floats per operand per stage (4608)
constexpr int GEMM_SMEM = 4 * STG * 4;   // 73,728 bytes

__global__ __launch_bounds__(256, 2)
void gemm_mma(const float* __restrict__ A, const float* __restrict__ Bw, float* __restrict__ C,
              int K, int lda, int ldb, int ldc, const float* __restrict__ bias)
{
    extern __shared__ float smem[];      // [stage0: A,B][stage1: A,B]
    const int tid = threadIdx.x;
    const int wid = tid >> 5, lane = tid & 31;
    const int wm = wid >> 2, wn = wid & 3;           // 2 x 4 warp grid
    const long m0 = (long)blockIdx.y * 128;
    const long n0 = (long)blockIdx.x * 128;

    const int r  = tid >> 3;
    const int c4 = (tid & 7) << 2;
    const uint32_t sbase = smem_u32(smem);
    const uint32_t aAddr0 = sbase + (uint32_t)((r * PADW + c4) * 4);
    const uint32_t bAddr0 = aAddr0 + (uint32_t)(STG * 4);
    const float* aSrc = A + (m0 + r) * (long)lda + c4;
    const float* bSrc = Bw + (n0 + r) * (long)ldb + c4;

    const int g = lane >> 2, t4 = lane & 3;
    const float* aF0 = smem + (wm * 64 + g) * PADW + t4;
    const float* bF0 = smem + STG + (wn * 32 + g) * PADW + t4;

    float acc[4][4][4];
#pragma unroll
    for (int i = 0; i < 4; i++)
#pragma unroll
        for (int j = 0; j < 4; j++)
#pragma unroll
            for (int l = 0; l < 4; l++) acc[i][j][l] = 0.f;

    const int nch = K / 32;

    auto issue = [&](int s, int c) {
        const uint32_t so = (uint32_t)(s * 2 * STG * 4);
        const long ko = (long)c * 32;
#pragma unroll
        for (int i = 0; i < 4; i++) {
            cpa16(aAddr0 + so + (uint32_t)(i * 32 * PADW * 4), aSrc + (long)(32 * i) * lda + ko);
            cpa16(bAddr0 + so + (uint32_t)(i * 32 * PADW * 4), bSrc + (long)(32 * i) * ldb + ko);
        }
        CP_COMMIT();
    };

    issue(0, 0);
    issue(1, 1);

    for (int c = 0; c < nch; c++) {
        if (c + 1 < nch) cp_wait<1>(); else cp_wait<0>();
        __syncthreads();

        const int s = c & 1;
        const float* Af = aF0 + s * 2 * STG;
        const float* Bf = bF0 + s * 2 * STG;
#pragma unroll
        for (int ks = 0; ks < 4; ks++) {
            uint32_t a[4][4], b[4][2];
#pragma unroll
            for (int mt = 0; mt < 4; mt++) {
                const float* p = Af + mt * 16 * PADW + ks * 8;
                a[mt][0] = __float_as_uint(p[0]);
                a[mt][1] = __float_as_uint(p[8 * PADW]);
                a[mt][2] = __float_as_uint(p[4]);
                a[mt][3] = __float_as_uint(p[8 * PADW + 4]);
            }
#pragma unroll
            for (int nt = 0; nt < 4; nt++) {
                const float* p = Bf + nt * 8 * PADW + ks * 8;
                b[nt][0] = __float_as_uint(p[0]);
                b[nt][1] = __float_as_uint(p[4]);
            }
#pragma unroll
            for (int mt = 0; mt < 4; mt++)
#pragma unroll
                for (int nt = 0; nt < 4; nt++)
                    mma_tf32(acc[mt][nt], a[mt], b[nt]);
        }
        __syncthreads();
        if (c + 2 < nch) issue(s, c + 2);
    }

    const long rowBase = m0 + wm * 64 + g;
#pragma unroll
    for (int mt = 0; mt < 4; mt++) {
        const long r0 = rowBase + mt * 16;
#pragma unroll
        for (int nt = 0; nt < 4; nt++) {
            const long col = n0 + wn * 32 + nt * 8 + t4 * 2;
            float2 v0 = make_float2(acc[mt][nt][0], acc[mt][nt][1]);
            float2 v1 = make_float2(acc[mt][nt][2], acc[mt][nt][3]);
            if (bias) {
                float2 bb = *(const float2*)&bias[col];
                v0.x += bb.x; v0.y += bb.y;
                v1.x += bb.x; v1.y += bb.y;
            }
            *(float2*)&C[r0 * (long)ldc + col] = v0;
            *(float2*)&C[(r0 + 8) * (long)ldc + col] = v1;
        }
    }
}

// ================= batched attention GEMM (mma.sync tf32) =================
// C[m,n] = alpha * sum_k A[m,k] * B(n,k), batched over blockIdx.z (z = b*8+h style).
// BKN=false: B is [N x K] k-contig (BN=128). BKN=true: B is [K x N] n-contig (BN=64).
// Bounds-guarded on M, N, K (zero-filled loads); tf32 rna rounding applied on load.
template<bool BKN>
__global__ __launch_bounds__(256)
void attn_mma(const float* __restrict__ A, const float* __restrict__ B, float* __restrict__ C,
              int M, int N, int K, int lda, int ldb, int ldc,
              long aOut, long aIn, long bOut, long bIn, long cOut, long cIn,
              float alpha)
{
    constexpr int BN = BKN ? 64 : 128;
    constexpr int NT = BKN ? 2 : 4;
    constexpr int AP = 36;
    constexpr int BP = BKN ? 72 : 36;

    __shared__ float As[64 * AP];
    __shared__ float Bs[BKN ? 32 * 72 : 128 * 36];

    const int z = blockIdx.z;
    A += (long)(z >> 3) * aOut + (long)(z & 7) * aIn;
    B += (long)(z >> 3) * bOut + (long)(z & 7) * bIn;
    C += (long)(z >> 3) * cOut + (long)(z & 7) * cIn;

    const int tid = threadIdx.x;
    const int wid = tid >> 5, lane = tid & 31;
    const int wm = wid >> 2, wn = wid & 3;      // 2 x 4 warp grid
    const int g = lane >> 2, t4 = lane & 3;
    const int m0 = blockIdx.y * 64;
    const int n0 = blockIdx.x * BN;

    const int lr = tid >> 3;            // 0..31
    const int lk = (tid & 7) << 2;      // 0,4,..,28

    float acc[2][NT][4];
#pragma unroll
    for (int i = 0; i < 2; i++)
#pragma unroll
        for (int j = 0; j < NT; j++)
#pragma unroll
            for (int l = 0; l < 4; l++) acc[i][j][l] = 0.f;

    for (int k0 = 0; k0 < K; k0 += 32) {
        // ---- load A tile: 64 x 32 ----
#pragma unroll
        for (int i = 0; i < 2; i++) {
            int row = lr + i * 32;
            float4 v = make_float4(0.f, 0.f, 0.f, 0.f);
            if (m0 + row < M && k0 + lk < K)
                v = *(const float4*)(A + (long)(m0 + row) * lda + k0 + lk);
            v.x = tf32r(v.x); v.y = tf32r(v.y); v.z = tf32r(v.z); v.w = tf32r(v.w);
            *(float4*)&As[row * AP + lk] = v;
        }
        // ---- load B tile ----
        if (!BKN) {
#pragma unroll
            for (int i = 0; i < BN / 32; i++) {
                int nrow = lr + i * 32;
                float4 v = make_float4(0.f, 0.f, 0.f, 0.f);
                if (n0 + nrow < N && k0 + lk < K)
                    v = *(const float4*)(B + (long)(n0 + nrow) * ldb + k0 + lk);
                v.x = tf32r(v.x); v.y = tf32r(v.y); v.z = tf32r(v.z); v.w = tf32r(v.w);
                *(float4*)&Bs[nrow * BP + lk] = v;
            }
        } else {
            const int kr = tid >> 4;            // 0..15
            const int ns = (tid & 15) << 2;     // 0,4,..,60
#pragma unroll
            for (int i = 0; i < 2; i++) {
                int krow = kr + i * 16;
                float4 v = make_float4(0.f, 0.f, 0.f, 0.f);
                if (k0 + krow < K && n0 + ns < N)
                    v = *(const float4*)(B + (long)(k0 + krow) * ldb + n0 + ns);
                v.x = tf32r(v.x); v.y = tf32r(v.y); v.z = tf32r(v.z); v.w = tf32r(v.w);
                *(float4*)&Bs[krow * BP + ns] = v;
            }
        }
        __syncthreads();

#pragma unroll
        for (int ks = 0; ks < 4; ks++) {
            uint32_t a[2][4], b[NT][2];
#pragma unroll
            for (int mt = 0; mt < 2; mt++) {
                const float* p = &As[(wm * 32 + mt * 16 + g) * AP + ks * 8 + t4];
                a[mt][0] = __float_as_uint(p[0]);
                a[mt][1] = __float_as_uint(p[8 * AP]);
                a[mt][2] = __float_as_uint(p[4]);
                a[mt][3] = __float_as_uint(p[8 * AP + 4]);
            }
#pragma unroll
            for (int nt = 0; nt < NT; nt++) {
                if (!BKN) {
                    const float* p = &Bs[(wn * 32 + nt * 8 + g) * BP + ks * 8 + t4];
                    b[nt][0] = __float_as_uint(p[0]);
                    b[nt][1] = __float_as_uint(p[4]);
                } else {
                    const int col = wn * 16 + nt * 8 + g;
                    b[nt][0] = __float_as_uint(Bs[(ks * 8 + t4) * BP + col]);
                    b[nt][1] = __float_as_uint(Bs[(ks * 8 + t4 + 4) * BP + col]);
                }
            }
#pragma unroll
            for (int mt = 0; mt < 2; mt++)
#pragma unroll
                for (int nt = 0; nt < NT; nt++)
                    mma_tf32(acc[mt][nt], a[mt], b[nt]);
        }
        __syncthreads();
    }

    // ---- epilogue (guarded, alpha scale) ----
#pragma unroll
    for (int mt = 0; mt < 2; mt++) {
        const int r0 = m0 + wm * 32 + mt * 16 + g;
#pragma unroll
        for (int nt = 0; nt < NT; nt++) {
            const int col = n0 + (BKN ? wn * 16 : wn * 32) + nt * 8 + t4 * 2;
            if (col < N) {
                if (r0 < M) {
                    float2 v = make_float2(alpha * acc[mt][nt][0], alpha * acc[mt][nt][1]);
                    *(float2*)&C[(long)r0 * ldc + col] = v;
                }
                if (r0 + 8 < M) {
                    float2 v = make_float2(alpha * acc[mt][nt][2], alpha * acc[mt][nt][3]);
                    *(float2*)&C[(long)(r0 + 8) * ldc + col] = v;
                }
            }
        }
    }
}

// ---------------- adaptive avg pool of q -> agent tokens ----------------
__global__ void pool_kernel(const float* __restrict__ qkv, float* __restrict__ agent)
{
    int b = blockIdx.x;
    int pq = blockIdx.y;
    int p = pq / POOL, q = pq % POOL;
    int ch = threadIdx.x;
    int hs = (p * HH) / POOL, he = ((p + 1) * HH + POOL - 1) / POOL;
    int ws = (q * HH) / POOL, we = ((q + 1) * HH + POOL - 1) / POOL;
    float inv = 1.0f / (float)((he - hs) * (we - ws));
    const float* base = qkv + (long)b * N_ * 1536;
    float s = 0.f;
    for (int h = hs; h < he; h++)
        for (int w = ws; w < we; w++)
            s += base[(long)(h * HH + w) * 1536 + ch];
    agent[((long)b * AG + pq) * C_ + ch] = s * inv;
}

// ---------------- softmax over rows of length rowLen (block per row) ----------------
__global__ void softmax_rows(float* __restrict__ S, int rowLen)
{
    float* row = S + (long)blockIdx.x * rowLen;
    const int tid = threadIdx.x;
    __shared__ float sm[8];
    __shared__ float bcast;

    float m = -3.4e38f;
    for (int i = tid; i < rowLen; i += 256) m = fmaxf(m, row[i]);
#pragma unroll
    for (int o = 16; o; o >>= 1) m = fmaxf(m, __shfl_xor_sync(0xffffffffu, m, o));
    if ((tid & 31) == 0) sm[tid >> 5] = m;
    __syncthreads();
    if (tid == 0) {
        float v = sm[0];
        for (int i = 1; i < 8; i++) v = fmaxf(v, sm[i]);
        bcast = v;
    }
    __syncthreads();
    m = bcast;

    float s = 0.f;
    for (int i = tid; i < rowLen; i += 256) {
        float e = __expf(row[i] - m);
        row[i] = e;
        s += e;
    }
#pragma unroll
    for (int o = 16; o; o >>= 1) s += __shfl_xor_sync(0xffffffffu, s, o);
    __syncthreads();
    if ((tid & 31) == 0) sm[tid >> 5] = s;
    __syncthreads();
    if (tid == 0) {
        float v = 0.f;
        for (int i = 0; i < 8; i++) v += sm[i];
        bcast = 1.0f / v;
    }
    __syncthreads();
    float inv = bcast;
    for (int i = tid; i < rowLen; i += 256) row[i] *= inv;
}

// ---------------- softmax over rows of length 144 (warp per row) ----------------
__global__ void softmax_small(float* __restrict__ S, long nrows)
{
    long gw = ((long)blockIdx.x * blockDim.x + threadIdx.x) >> 5;
    if (gw >= nrows) return;
    int lane = threadIdx.x & 31;
    float* row = S + gw * 144;
    float v[5];
    float m = -3.4e38f;
#pragma unroll
    for (int j = 0; j < 5; j++) {
        int i = lane + j * 32;
        v[j] = (i < 144) ? row[i] : -3.4e38f;
        m = fmaxf(m, v[j]);
    }
#pragma unroll
    for (int o = 16; o; o >>= 1) m = fmaxf(m, __shfl_xor_sync(0xffffffffu, m, o));
    float s = 0.f;
#pragma unroll
    for (int j = 0; j < 5; j++) {
        int i = lane + j * 32;
        if (i < 144) { v[j] = __expf(v[j] - m); s += v[j]; }
    }
#pragma unroll
    for (int o = 16; o; o >>= 1) s += __shfl_xor_sync(0xffffffffu, s, o);
    float inv = 1.0f / s;
#pragma unroll
    for (int j = 0; j < 5; j++) {
        int i = lane + j * 32;
        if (i < 144) row[i] = v[j] * inv;
    }
}

// ---------------- depthwise 3x3 conv on v + bias, residual add into y ----------------
__global__ void dwc_add(const float* __restrict__ qkv, const float* __restrict__ w,
                        const float* __restrict__ bias, float* __restrict__ y)
{
    long idx = (long)blockIdx.x * blockDim.x + threadIdx.x;
    if (idx >= Y_ELEMS) return;
    int ch = (int)(idx & (C_ - 1));
    long t = idx >> 9;
    int l = (int)(t % N_);
    int b = (int)(t / N_);
    int hh = l / HH, ww = l % HH;
    const float* vbase = qkv + (long)b * N_ * 1536 + 1024 + ch;
    float s = bias[ch];
#pragma unroll
    for (int kh = 0; kh < 3; kh++) {
        int h2 = hh + kh - 1;
        if (h2 < 0 || h2 >= HH) continue;
#pragma unroll
        for (int kw = 0; kw < 3; kw++) {
            int w2 = ww + kw - 1;
            if (w2 < 0 || w2 >= HH) continue;
            s = fmaf(vbase[(long)(h2 * HH + w2) * 1536], w[ch * 9 + kh * 3 + kw], s);
        }
    }
    y[idx] += s;
}

// ---------------- launch ----------------
extern "C" void kernel_launch(void* const* d_in, const int* in_sizes, int n_in,
                              void* d_out, int out_size)
{
    const float* x      = (const float*)d_in[0];
    const float* qkv_w  = (const float*)d_in[1];
    const float* proj_w = (const float*)d_in[2];
    const float* proj_b = (const float*)d_in[3];
    const float* dwc_w  = (const float*)d_in[4];
    const float* dwc_b  = (const float*)d_in[5];
    float* out = (float*)d_out;

    float *qkv, *agent, *S, *av, *y, *wr;
    cudaGetSymbolAddress((void**)&qkv,   g_qkv);
    cudaGetSymbolAddress((void**)&agent, g_agent);
    cudaGetSymbolAddress((void**)&S,     g_S);
    cudaGetSymbolAddress((void**)&av,    g_av);
    cudaGetSymbolAddress((void**)&y,     g_y);
    cudaGetSymbolAddress((void**)&wr,    g_wr);

    cudaFuncSetAttribute(gemm_mma, cudaFuncAttributeMaxDynamicSharedMemorySize, GEMM_SMEM);

    const long BQKV = (long)N_ * 1536;
    const float scale = 0.125f;

    // 0) tf32-round x (into y scratch, free until step 8) and qkv_w
    {
        long n4 = Y_ELEMS / 4;
        round_copy<<<(int)((n4 + 255) / 256), 256>>>(x, y, n4);
        long w4 = 786432 / 4;
        round_copy<<<(int)((w4 + 255) / 256), 256>>>(qkv_w, wr, w4);
    }

    // 1) qkv = x @ qkv_w^T : [50176 x 1536]   (mma.sync tf32)
    gemm_mma<<<dim3(12, 392), 256, GEMM_SMEM>>>(y, wr, qkv, 512, 512, 512, 1536, nullptr);

    // 2) agent tokens = adaptive 12x12 pool of q
    pool_kernel<<<dim3(B_, AG), 512>>>(qkv, agent);

    // 3) stage-1 logits: S[z,p,l] = scale * ah @ kh^T   (M=144, N=3136, K=64)
    attn_mma<false><<<dim3(25, 3, 128), 256>>>(
        agent, qkv + 512, S, AG, N_, 64, 512, 1536, N_,
        (long)AG * C_, 64, BQKV, 64, 8L * AG * N_, (long)AG * N_, scale);

    // 4) softmax over l (rows of 3136)
    softmax_rows<<<B_ * H_ * AG, 256>>>(S, N_);

    // 5) agent_v[z,p,d] = S @ vh   (M=144, N=64, K=3136)
    attn_mma<true><<<dim3(1, 3, 128), 256>>>(
        S, qkv + 1024, av, AG, 64, N_, N_, 1536, 64,
        8L * AG * N_, (long)AG * N_, BQKV, 64, 8L * AG * 64, (long)AG * 64, 1.f);

    // 6) stage-2 logits: S[z,l,p] = scale * qh @ ah^T   (M=3136, N=144, K=64)
    attn_mma<false><<<dim3(2, 49, 128), 256>>>(
        qkv, agent, S, N_, AG, 64, 1536, 512, AG,
        BQKV, 64, (long)AG * C_, 64, 8L * N_ * AG, (long)N_ * AG, scale);

    // 7) softmax over p (rows of 144)
    {
        long nrows = (long)B_ * H_ * N_;
        int blocks = (int)((nrows * 32 + 255) / 256);
        softmax_small<<<blocks, 256>>>(S, nrows);
    }

    // 8) y[b,l,h*64+d] = S @ agent_v   (M=3136, N=64, K=144)
    attn_mma<true><<<dim3(1, 49, 128), 256>>>(
        S, av, y, N_, 64, AG, AG, 64, C_,
        8L * N_ * AG, (long)N_ * AG, 8L * AG * 64, (long)AG * 64,
        (long)N_ * C_, 64, 1.f);

    // 9) y += depthwise3x3(v) + dwc_b
    {
        int blocks = (int)((Y_ELEMS + 255) / 256);
        dwc_add<<<blocks, 256>>>(qkv, dwc_w, dwc_b, y);
    }

    // 9.5) tf32-round y (in place) and proj_w
    {
        long n4 = Y_ELEMS / 4;
        round_copy<<<(int)((n4 + 255) / 256), 256>>>(y, y, n4);
        long w4 = 262144 / 4;
        round_copy<<<(int)((w4 + 255) / 256), 256>>>(proj_w, wr, w4);
    }

    // 10) out = y @ proj_w^T + proj_b   (mma.sync tf32)
    gemm_mma<<<dim3(4, 392), 256, GEMM_SMEM>>>(y, wr, out, 512, 512, 512, 512, proj_b);
}

// round 9
// speedup vs baseline: 2.9385x; 1.1383x over previous
#include <cuda_runtime.h>
#include <cstdint>
#include <math.h>

// ---------------- problem constants ----------------
constexpr int B_ = 16, N_ = 3136, C_ = 512, H_ = 8, D_ = 64;
constexpr int HH = 56, POOL = 12, AG = 144;
constexpr long M_ = (long)B_ * N_;                 // 50176
constexpr long QKV_ELEMS = M_ * 3 * C_;            // 77,070,336
constexpr long AGENT_ELEMS = (long)B_ * AG * C_;   // 1,179,648
constexpr long S_ELEMS = (long)B_ * H_ * AG * N_;  // 57,802,752 (stage-1 only now)
constexpr long AV_ELEMS = (long)B_ * H_ * AG * D_; // 1,179,648
constexpr long Y_ELEMS = M_ * C_;                  // 25,690,112

// ---------------- scratch (static device globals; no allocations) ----------------
__device__ float g_qkv[QKV_ELEMS];
__device__ float g_agent[AGENT_ELEMS];
__device__ float g_S[S_ELEMS];
__device__ float g_av[AV_ELEMS];
__device__ float g_y[Y_ELEMS];
__device__ float g_wr[786432];   // rounded weights (qkv_w 786432; proj_w 262144 fits)

// ================= small helpers =================
__device__ __forceinline__ uint32_t smem_u32(const void* p) {
    uint32_t a;
    asm("{ .reg .u64 t; cvta.to.shared.u64 t, %1; cvt.u32.u64 %0, t; }" : "=r"(a) : "l"(p));
    return a;
}
__device__ __forceinline__ float tf32r(float f) {
    uint32_t r;
    asm("cvt.rna.tf32.f32 %0, %1;" : "=r"(r) : "f"(f));
    return __uint_as_float(r);
}
__device__ __forceinline__ void cpa16(uint32_t dst, const float* src) {
    asm volatile("cp.async.cg.shared.global [%0], [%1], 16;" :: "r"(dst), "l"(src));
}
#define CP_COMMIT() asm volatile("cp.async.commit_group;" ::: "memory")
template<int N> __device__ __forceinline__ void cp_wait() {
    asm volatile("cp.async.wait_group %0;" :: "n"(N) : "memory");
}
__device__ __forceinline__ void mma_tf32(float* c, const uint32_t* a, const uint32_t* b) {
    asm volatile(
        "mma.sync.aligned.m16n8k8.row.col.f32.tf32.tf32.f32 "
        "{%0,%1,%2,%3}, {%4,%5,%6,%7}, {%8,%9}, {%0,%1,%2,%3};"
        : "+f"(c[0]), "+f"(c[1]), "+f"(c[2]), "+f"(c[3])
        : "r"(a[0]), "r"(a[1]), "r"(a[2]), "r"(a[3]), "r"(b[0]), "r"(b[1]));
}

// ---------------- tf32 rounding pre-pass (float4 granularity) ----------------
__global__ void round_copy(const float* __restrict__ in, float* __restrict__ out, long n4)
{
    long i = (long)blockIdx.x * blockDim.x + threadIdx.x;
    if (i >= n4) return;
    float4 v = ((const float4*)in)[i];
    v.x = tf32r(v.x); v.y = tf32r(v.y); v.z = tf32r(v.z); v.w = tf32r(v.w);
    ((float4*)out)[i] = v;
}

// ================= large tensor-core GEMM (qkv / proj) =================
constexpr int PADW = 36;
constexpr int STG  = 128 * PADW;
constexpr int GEMM_SMEM = 4 * STG * 4;   // 73,728 bytes

__global__ __launch_bounds__(256, 2)
void gemm_mma(const float* __restrict__ A, const float* __restrict__ Bw, float* __restrict__ C,
              int K, int lda, int ldb, int ldc, const float* __restrict__ bias)
{
    extern __shared__ float smem[];
    const int tid = threadIdx.x;
    const int wid = tid >> 5, lane = tid & 31;
    const int wm = wid >> 2, wn = wid & 3;
    const long m0 = (long)blockIdx.y * 128;
    const long n0 = (long)blockIdx.x * 128;

    const int r  = tid >> 3;
    const int c4 = (tid & 7) << 2;
    const uint32_t sbase = smem_u32(smem);
    const uint32_t aAddr0 = sbase + (uint32_t)((r * PADW + c4) * 4);
    const uint32_t bAddr0 = aAddr0 + (uint32_t)(STG * 4);
    const float* aSrc = A + (m0 + r) * (long)lda + c4;
    const float* bSrc = Bw + (n0 + r) * (long)ldb + c4;

    const int g = lane >> 2, t4 = lane & 3;
    const float* aF0 = smem + (wm * 64 + g) * PADW + t4;
    const float* bF0 = smem + STG + (wn * 32 + g) * PADW + t4;

    float acc[4][4][4];
#pragma unroll
    for (int i = 0; i < 4; i++)
#pragma unroll
        for (int j = 0; j < 4; j++)
#pragma unroll
            for (int l = 0; l < 4; l++) acc[i][j][l] = 0.f;

    const int nch = K / 32;

    auto issue = [&](int s, int c) {
        const uint32_t so = (uint32_t)(s * 2 * STG * 4);
        const long ko = (long)c * 32;
#pragma unroll
        for (int i = 0; i < 4; i++) {
            cpa16(aAddr0 + so + (uint32_t)(i * 32 * PADW * 4), aSrc + (long)(32 * i) * lda + ko);
            cpa16(bAddr0 + so + (uint32_t)(i * 32 * PADW * 4), bSrc + (long)(32 * i) * ldb + ko);
        }
        CP_COMMIT();
    };

    issue(0, 0);
    issue(1, 1);

    for (int c = 0; c < nch; c++) {
        if (c + 1 < nch) cp_wait<1>(); else cp_wait<0>();
        __syncthreads();

        const int s = c & 1;
        const float* Af = aF0 + s * 2 * STG;
        const float* Bf = bF0 + s * 2 * STG;
#pragma unroll
        for (int ks = 0; ks < 4; ks++) {
            uint32_t a[4][4], b[4][2];
#pragma unroll
            for (int mt = 0; mt < 4; mt++) {
                const float* p = Af + mt * 16 * PADW + ks * 8;
                a[mt][0] = __float_as_uint(p[0]);
                a[mt][1] = __float_as_uint(p[8 * PADW]);
                a[mt][2] = __float_as_uint(p[4]);
                a[mt][3] = __float_as_uint(p[8 * PADW + 4]);
            }
#pragma unroll
            for (int nt = 0; nt < 4; nt++) {
                const float* p = Bf + nt * 8 * PADW + ks * 8;
                b[nt][0] = __float_as_uint(p[0]);
                b[nt][1] = __float_as_uint(p[4]);
            }
#pragma unroll
            for (int mt = 0; mt < 4; mt++)
#pragma unroll
                for (int nt = 0; nt < 4; nt++)
                    mma_tf32(acc[mt][nt], a[mt], b[nt]);
        }
        __syncthreads();
        if (c + 2 < nch) issue(s, c + 2);
    }

    const long rowBase = m0 + wm * 64 + g;
#pragma unroll
    for (int mt = 0; mt < 4; mt++) {
        const long r0 = rowBase + mt * 16;
#pragma unroll
        for (int nt = 0; nt < 4; nt++) {
            const long col = n0 + wn * 32 + nt * 8 + t4 * 2;
            float2 v0 = make_float2(acc[mt][nt][0], acc[mt][nt][1]);
            float2 v1 = make_float2(acc[mt][nt][2], acc[mt][nt][3]);
            if (bias) {
                float2 bb = *(const float2*)&bias[col];
                v0.x += bb.x; v0.y += bb.y;
                v1.x += bb.x; v1.y += bb.y;
            }
            *(float2*)&C[r0 * (long)ldc + col] = v0;
            *(float2*)&C[(r0 + 8) * (long)ldc + col] = v1;
        }
    }
}

// ================= batched attention GEMM (stages 3 & 5) =================
template<bool BKN>
__global__ __launch_bounds__(256)
void attn_mma(const float* __restrict__ A, const float* __restrict__ B, float* __restrict__ C,
              int M, int N, int K, int lda, int ldb, int ldc,
              long aOut, long aIn, long bOut, long bIn, long cOut, long cIn,
              float alpha)
{
    constexpr int BN = BKN ? 64 : 128;
    constexpr int NT = BKN ? 2 : 4;
    constexpr int AP = 36;
    constexpr int BP = BKN ? 72 : 36;

    __shared__ float As[64 * AP];
    __shared__ float Bs[BKN ? 32 * 72 : 128 * 36];

    const int z = blockIdx.z;
    A += (long)(z >> 3) * aOut + (long)(z & 7) * aIn;
    B += (long)(z >> 3) * bOut + (long)(z & 7) * bIn;
    C += (long)(z >> 3) * cOut + (long)(z & 7) * cIn;

    const int tid = threadIdx.x;
    const int wid = tid >> 5, lane = tid & 31;
    const int wm = wid >> 2, wn = wid & 3;
    const int g = lane >> 2, t4 = lane & 3;
    const int m0 = blockIdx.y * 64;
    const int n0 = blockIdx.x * BN;

    const int lr = tid >> 3;
    const int lk = (tid & 7) << 2;

    float acc[2][NT][4];
#pragma unroll
    for (int i = 0; i < 2; i++)
#pragma unroll
        for (int j = 0; j < NT; j++)
#pragma unroll
            for (int l = 0; l < 4; l++) acc[i][j][l] = 0.f;

    for (int k0 = 0; k0 < K; k0 += 32) {
#pragma unroll
        for (int i = 0; i < 2; i++) {
            int row = lr + i * 32;
            float4 v = make_float4(0.f, 0.f, 0.f, 0.f);
            if (m0 + row < M && k0 + lk < K)
                v = *(const float4*)(A + (long)(m0 + row) * lda + k0 + lk);
            v.x = tf32r(v.x); v.y = tf32r(v.y); v.z = tf32r(v.z); v.w = tf32r(v.w);
            *(float4*)&As[row * AP + lk] = v;
        }
        if (!BKN) {
#pragma unroll
            for (int i = 0; i < BN / 32; i++) {
                int nrow = lr + i * 32;
                float4 v = make_float4(0.f, 0.f, 0.f, 0.f);
                if (n0 + nrow < N && k0 + lk < K)
                    v = *(const float4*)(B + (long)(n0 + nrow) * ldb + k0 + lk);
                v.x = tf32r(v.x); v.y = tf32r(v.y); v.z = tf32r(v.z); v.w = tf32r(v.w);
                *(float4*)&Bs[nrow * BP + lk] = v;
            }
        } else {
            const int kr = tid >> 4;
            const int ns = (tid & 15) << 2;
#pragma unroll
            for (int i = 0; i < 2; i++) {
                int krow = kr + i * 16;
                float4 v = make_float4(0.f, 0.f, 0.f, 0.f);
                if (k0 + krow < K && n0 + ns < N)
                    v = *(const float4*)(B + (long)(k0 + krow) * ldb + n0 + ns);
                v.x = tf32r(v.x); v.y = tf32r(v.y); v.z = tf32r(v.z); v.w = tf32r(v.w);
                *(float4*)&Bs[krow * BP + ns] = v;
            }
        }
        __syncthreads();

#pragma unroll
        for (int ks = 0; ks < 4; ks++) {
            uint32_t a[2][4], b[NT][2];
#pragma unroll
            for (int mt = 0; mt < 2; mt++) {
                const float* p = &As[(wm * 32 + mt * 16 + g) * AP + ks * 8 + t4];
                a[mt][0] = __float_as_uint(p[0]);
                a[mt][1] = __float_as_uint(p[8 * AP]);
                a[mt][2] = __float_as_uint(p[4]);
                a[mt][3] = __float_as_uint(p[8 * AP + 4]);
            }
#pragma unroll
            for (int nt = 0; nt < NT; nt++) {
                if (!BKN) {
                    const float* p = &Bs[(wn * 32 + nt * 8 + g) * BP + ks * 8 + t4];
                    b[nt][0] = __float_as_uint(p[0]);
                    b[nt][1] = __float_as_uint(p[4]);
                } else {
                    const int col = wn * 16 + nt * 8 + g;
                    b[nt][0] = __float_as_uint(Bs[(ks * 8 + t4) * BP + col]);
                    b[nt][1] = __float_as_uint(Bs[(ks * 8 + t4 + 4) * BP + col]);
                }
            }
#pragma unroll
            for (int mt = 0; mt < 2; mt++)
#pragma unroll
                for (int nt = 0; nt < NT; nt++)
                    mma_tf32(acc[mt][nt], a[mt], b[nt]);
        }
        __syncthreads();
    }

#pragma unroll
    for (int mt = 0; mt < 2; mt++) {
        const int r0 = m0 + wm * 32 + mt * 16 + g;
#pragma unroll
        for (int nt = 0; nt < NT; nt++) {
            const int col = n0 + (BKN ? wn * 16 : wn * 32) + nt * 8 + t4 * 2;
            if (col < N) {
                if (r0 < M) {
                    float2 v = make_float2(alpha * acc[mt][nt][0], alpha * acc[mt][nt][1]);
                    *(float2*)&C[(long)r0 * ldc + col] = v;
                }
                if (r0 + 8 < M) {
                    float2 v = make_float2(alpha * acc[mt][nt][2], alpha * acc[mt][nt][3]);
                    *(float2*)&C[(long)(r0 + 8) * ldc + col] = v;
                }
            }
        }
    }
}

// ================= fused stage-2: logits + softmax + @agent_v =================
// Per CTA: z = blockIdx.y (b*8+h), 128 q-rows (blockIdx.x). Computes
// y[rows, h*64:..] = softmax(scale * qh @ agent_h^T) @ agent_v  with no HBM S buffer.
// smem: Ps[128][148] (75,776B, aliases As[128][68]+Bs[144][68]) + Vs[144][72] (41,472B).
constexpr int S2_AP = 68, S2_BP = 68, S2_PP = 148, S2_VP = 72;
constexpr int S2_VS_OFF = 128 * S2_PP;                    // floats
constexpr int S2_SMEM = (S2_VS_OFF + AG * S2_VP) * 4;     // 117,248 bytes

__global__ __launch_bounds__(256)
void stage2_fused(const float* __restrict__ Q, const float* __restrict__ Ag,
                  const float* __restrict__ Av, float* __restrict__ Y, float scale)
{
    extern __shared__ float sm[];
    float* As = sm;                    // [128][68] (aliases Ps)
    float* Bs = sm + 128 * S2_AP;      // [144][68] (aliases Ps)
    float* Ps = sm;                    // [128][148]
    float* Vs = sm + S2_VS_OFF;        // [144][72]

    const int z = blockIdx.y;
    const int b = z >> 3, h = z & 7;
    const float* Qz = Q + (long)b * N_ * 1536 + h * 64;
    const float* Agz = Ag + (long)b * AG * C_ + h * 64;
    const float* Avz = Av + (long)z * AG * 64;
    float* Yz = g_y + (long)b * N_ * C_ + h * 64;   // placeholder; real Y passed below
    Yz = Y + (long)b * N_ * C_ + h * 64;

    const int tid = threadIdx.x;
    const int wid = tid >> 5, lane = tid & 31;
    const int g = lane >> 2, t4 = lane & 3;
    const int m0 = blockIdx.x * 128;

    // ---- load Q tile [128 x 64] ----
#pragma unroll
    for (int i = 0; i < 8; i++) {
        int idx = tid + i * 256;           // 0..2047
        int row = idx >> 4, c4 = (idx & 15) << 2;
        float4 v = make_float4(0.f, 0.f, 0.f, 0.f);
        if (m0 + row < N_)
            v = *(const float4*)(Qz + (long)(m0 + row) * 1536 + c4);
        v.x = tf32r(v.x); v.y = tf32r(v.y); v.z = tf32r(v.z); v.w = tf32r(v.w);
        *(float4*)&As[row * S2_AP + c4] = v;
    }
    // ---- load agent tile [144 x 64] ----
#pragma unroll
    for (int i = 0; i < 9; i++) {
        int idx = tid + i * 256;           // 0..2303
        int row = idx >> 4, c4 = (idx & 15) << 2;
        float4 v = *(const float4*)(Agz + (long)row * C_ + c4);
        v.x = tf32r(v.x); v.y = tf32r(v.y); v.z = tf32r(v.z); v.w = tf32r(v.w);
        *(float4*)&Bs[row * S2_BP + c4] = v;
    }
    // ---- load agent_v [144 x 64] ----
#pragma unroll
    for (int i = 0; i < 9; i++) {
        int idx = tid + i * 256;
        int row = idx >> 4, c4 = (idx & 15) << 2;
        float4 v = *(const float4*)(Avz + (long)row * 64 + c4);
        v.x = tf32r(v.x); v.y = tf32r(v.y); v.z = tf32r(v.z); v.w = tf32r(v.w);
        *(float4*)&Vs[row * S2_VP + c4] = v;
    }
    __syncthreads();

    // ---- phase 1: logits L[128 x 144] ----
    const int r = wid * 16 + g;            // local row
    float accL[18][4];
#pragma unroll
    for (int nt = 0; nt < 18; nt++)
#pragma unroll
        for (int l = 0; l < 4; l++) accL[nt][l] = 0.f;

#pragma unroll
    for (int ks = 0; ks < 8; ks++) {
        uint32_t a[4];
        {
            const float* p = &As[r * S2_AP + ks * 8 + t4];
            a[0] = __float_as_uint(p[0]);
            a[1] = __float_as_uint(p[8 * S2_AP]);
            a[2] = __float_as_uint(p[4]);
            a[3] = __float_as_uint(p[8 * S2_AP + 4]);
        }
#pragma unroll
        for (int nt = 0; nt < 18; nt++) {
            uint32_t bfr[2];
            const float* p = &Bs[(nt * 8 + g) * S2_BP + ks * 8 + t4];
            bfr[0] = __float_as_uint(p[0]);
            bfr[1] = __float_as_uint(p[4]);
            mma_tf32(accL[nt], a, bfr);
        }
    }

    // ---- softmax over 144 (per row; row spread over quad t4=0..3) ----
    float m0r = -3.4e38f, m1r = -3.4e38f;
#pragma unroll
    for (int nt = 0; nt < 18; nt++) {
        m0r = fmaxf(m0r, fmaxf(accL[nt][0], accL[nt][1]));
        m1r = fmaxf(m1r, fmaxf(accL[nt][2], accL[nt][3]));
    }
    m0r *= scale; m1r *= scale;
#pragma unroll
    for (int o = 1; o < 4; o <<= 1) {
        m0r = fmaxf(m0r, __shfl_xor_sync(0xffffffffu, m0r, o));
        m1r = fmaxf(m1r, __shfl_xor_sync(0xffffffffu, m1r, o));
    }
    float s0 = 0.f, s1 = 0.f;
#pragma unroll
    for (int nt = 0; nt < 18; nt++) {
        accL[nt][0] = __expf(accL[nt][0] * scale - m0r); s0 += accL[nt][0];
        accL[nt][1] = __expf(accL[nt][1] * scale - m0r); s0 += accL[nt][1];
        accL[nt][2] = __expf(accL[nt][2] * scale - m1r); s1 += accL[nt][2];
        accL[nt][3] = __expf(accL[nt][3] * scale - m1r); s1 += accL[nt][3];
    }
#pragma unroll
    for (int o = 1; o < 4; o <<= 1) {
        s0 += __shfl_xor_sync(0xffffffffu, s0, o);
        s1 += __shfl_xor_sync(0xffffffffu, s1, o);
    }
    const float inv0 = 1.0f / s0, inv1 = 1.0f / s1;

    __syncthreads();   // all As/Bs reads done before Ps overwrite

    // ---- write P (tf32-rounded) ----
#pragma unroll
    for (int nt = 0; nt < 18; nt++) {
        const int col = nt * 8 + 2 * t4;
        Ps[r * S2_PP + col]       = tf32r(accL[nt][0] * inv0);
        Ps[r * S2_PP + col + 1]   = tf32r(accL[nt][1] * inv0);
        Ps[(r + 8) * S2_PP + col]     = tf32r(accL[nt][2] * inv1);
        Ps[(r + 8) * S2_PP + col + 1] = tf32r(accL[nt][3] * inv1);
    }
    __syncthreads();

    // ---- phase 3: out = P @ agent_v  [128 x 64] ----
    float acc2[8][4];
#pragma unroll
    for (int nt = 0; nt < 8; nt++)
#pragma unroll
        for (int l = 0; l < 4; l++) acc2[nt][l] = 0.f;

#pragma unroll
    for (int ks = 0; ks < 18; ks++) {
        uint32_t a[4];
        {
            const float* p = &Ps[r * S2_PP + ks * 8 + t4];
            a[0] = __float_as_uint(p[0]);
            a[1] = __float_as_uint(p[8 * S2_PP]);
            a[2] = __float_as_uint(p[4]);
            a[3] = __float_as_uint(p[8 * S2_PP + 4]);
        }
#pragma unroll
        for (int nt = 0; nt < 8; nt++) {
            uint32_t bfr[2];
            bfr[0] = __float_as_uint(Vs[(ks * 8 + t4) * S2_VP + nt * 8 + g]);
            bfr[1] = __float_as_uint(Vs[(ks * 8 + t4 + 4) * S2_VP + nt * 8 + g]);
            mma_tf32(acc2[nt], a, bfr);
        }
    }

    // ---- epilogue ----
    const int gr = m0 + r;
#pragma unroll
    for (int nt = 0; nt < 8; nt++) {
        const int col = nt * 8 + 2 * t4;
        if (gr < N_)
            *(float2*)&Yz[(long)gr * C_ + col] = make_float2(acc2[nt][0], acc2[nt][1]);
        if (gr + 8 < N_)
            *(float2*)&Yz[(long)(gr + 8) * C_ + col] = make_float2(acc2[nt][2], acc2[nt][3]);
    }
}

// ---------------- adaptive avg pool of q -> agent tokens ----------------
__global__ void pool_kernel(const float* __restrict__ qkv, float* __restrict__ agent)
{
    int b = blockIdx.x;
    int pq = blockIdx.y;
    int p = pq / POOL, q = pq % POOL;
    int ch = threadIdx.x;
    int hs = (p * HH) / POOL, he = ((p + 1) * HH + POOL - 1) / POOL;
    int ws = (q * HH) / POOL, we = ((q + 1) * HH + POOL - 1) / POOL;
    float inv = 1.0f / (float)((he - hs) * (we - ws));
    const float* base = qkv + (long)b * N_ * 1536;
    float s = 0.f;
    for (int h = hs; h < he; h++)
        for (int w = ws; w < we; w++)
            s += base[(long)(h * HH + w) * 1536 + ch];
    agent[((long)b * AG + pq) * C_ + ch] = s * inv;
}

// ---------------- softmax over rows of length rowLen (block per row) ----------------
__global__ void softmax_rows(float* __restrict__ S, int rowLen)
{
    float* row = S + (long)blockIdx.x * rowLen;
    const int tid = threadIdx.x;
    __shared__ float sm[8];
    __shared__ float bcast;

    float m = -3.4e38f;
    for (int i = tid; i < rowLen; i += 256) m = fmaxf(m, row[i]);
#pragma unroll
    for (int o = 16; o; o >>= 1) m = fmaxf(m, __shfl_xor_sync(0xffffffffu, m, o));
    if ((tid & 31) == 0) sm[tid >> 5] = m;
    __syncthreads();
    if (tid == 0) {
        float v = sm[0];
        for (int i = 1; i < 8; i++) v = fmaxf(v, sm[i]);
        bcast = v;
    }
    __syncthreads();
    m = bcast;

    float s = 0.f;
    for (int i = tid; i < rowLen; i += 256) {
        float e = __expf(row[i] - m);
        row[i] = e;
        s += e;
    }
#pragma unroll
    for (int o = 16; o; o >>= 1) s += __shfl_xor_sync(0xffffffffu, s, o);
    __syncthreads();
    if ((tid & 31) == 0) sm[tid >> 5] = s;
    __syncthreads();
    if (tid == 0) {
        float v = 0.f;
        for (int i = 0; i < 8; i++) v += sm[i];
        bcast = 1.0f / v;
    }
    __syncthreads();
    float inv = bcast;
    for (int i = tid; i < rowLen; i += 256) row[i] *= inv;
}

// ---------------- depthwise 3x3 conv on v + bias, residual add into y (tf32-rounded) ----------------
__global__ void dwc_add(const float* __restrict__ qkv, const float* __restrict__ w,
                        const float* __restrict__ bias, float* __restrict__ y)
{
    long idx = (long)blockIdx.x * blockDim.x + threadIdx.x;
    if (idx >= Y_ELEMS) return;
    int ch = (int)(idx & (C_ - 1));
    long t = idx >> 9;
    int l = (int)(t % N_);
    int b = (int)(t / N_);
    int hh = l / HH, ww = l % HH;
    const float* vbase = qkv + (long)b * N_ * 1536 + 1024 + ch;
    float s = bias[ch];
#pragma unroll
    for (int kh = 0; kh < 3; kh++) {
        int h2 = hh + kh - 1;
        if (h2 < 0 || h2 >= HH) continue;
#pragma unroll
        for (int kw = 0; kw < 3; kw++) {
            int w2 = ww + kw - 1;
            if (w2 < 0 || w2 >= HH) continue;
            s = fmaf(vbase[(long)(h2 * HH + w2) * 1536], w[ch * 9 + kh * 3 + kw], s);
        }
    }
    y[idx] = tf32r(y[idx] + s);   // fold tf32 rounding for proj GEMM input
}

// ---------------- launch ----------------
extern "C" void kernel_launch(void* const* d_in, const int* in_sizes, int n_in,
                              void* d_out, int out_size)
{
    const float* x      = (const float*)d_in[0];
    const float* qkv_w  = (const float*)d_in[1];
    const float* proj_w = (const float*)d_in[2];
    const float* proj_b = (const float*)d_in[3];
    const float* dwc_w  = (const float*)d_in[4];
    const float* dwc_b  = (const float*)d_in[5];
    float* out = (float*)d_out;

    float *qkv, *agent, *S, *av, *y, *wr;
    cudaGetSymbolAddress((void**)&qkv,   g_qkv);
    cudaGetSymbolAddress((void**)&agent, g_agent);
    cudaGetSymbolAddress((void**)&S,     g_S);
    cudaGetSymbolAddress((void**)&av,    g_av);
    cudaGetSymbolAddress((void**)&y,     g_y);
    cudaGetSymbolAddress((void**)&wr,    g_wr);

    cudaFuncSetAttribute(gemm_mma, cudaFuncAttributeMaxDynamicSharedMemorySize, GEMM_SMEM);
    cudaFuncSetAttribute(stage2_fused, cudaFuncAttributeMaxDynamicSharedMemorySize, S2_SMEM);

    const long BQKV = (long)N_ * 1536;
    const float scale = 0.125f;

    // 0) tf32-round x (into y scratch) and qkv_w
    {
        long n4 = Y_ELEMS / 4;
        round_copy<<<(int)((n4 + 255) / 256), 256>>>(x, y, n4);
        long w4 = 786432 / 4;
        round_copy<<<(int)((w4 + 255) / 256), 256>>>(qkv_w, wr, w4);
    }

    // 1) qkv = x @ qkv_w^T
    gemm_mma<<<dim3(12, 392), 256, GEMM_SMEM>>>(y, wr, qkv, 512, 512, 512, 1536, nullptr);

    // 2) agent tokens
    pool_kernel<<<dim3(B_, AG), 512>>>(qkv, agent);

    // 3) stage-1 logits: S[z,p,l] = scale * ah @ kh^T
    attn_mma<false><<<dim3(25, 3, 128), 256>>>(
        agent, qkv + 512, S, AG, N_, 64, 512, 1536, N_,
        (long)AG * C_, 64, BQKV, 64, 8L * AG * N_, (long)AG * N_, scale);

    // 4) softmax over l (rows of 3136)
    softmax_rows<<<B_ * H_ * AG, 256>>>(S, N_);

    // 5) agent_v = S @ vh
    attn_mma<true><<<dim3(1, 3, 128), 256>>>(
        S, qkv + 1024, av, AG, 64, N_, N_, 1536, 64,
        8L * AG * N_, (long)AG * N_, BQKV, 64, 8L * AG * 64, (long)AG * 64, 1.f);

    // 6+7+8) fused: y = softmax(scale * qh @ agent^T) @ agent_v
    stage2_fused<<<dim3(25, 128), 256, S2_SMEM>>>(qkv, agent, av, y, scale);

    // 9) y = tf32r(y + depthwise3x3(v) + dwc_b)
    {
        int blocks = (int)((Y_ELEMS + 255) / 256);
        dwc_add<<<blocks, 256>>>(qkv, dwc_w, dwc_b, y);
    }

    // 9.5) tf32-round proj_w only (y already rounded by dwc_add)
    {
        long w4 = 262144 / 4;
        round_copy<<<(int)((w4 + 255) / 256), 256>>>(proj_w, wr, w4);
    }

    // 10) out = y @ proj_w^T + proj_b
    gemm_mma<<<dim3(4, 392), 256, GEMM_SMEM>>>(y, wr, out, 512, 512, 512, 512, proj_b);
}

// round 10
// speedup vs baseline: 3.3381x; 1.1360x over previous
#include <cuda_runtime.h>
#include <cstdint>
#include <math.h>

// ---------------- problem constants ----------------
constexpr int B_ = 16, N_ = 3136, C_ = 512, H_ = 8, D_ = 64;
constexpr int HH = 56, POOL = 12, AG = 144;
constexpr long M_ = (long)B_ * N_;                 // 50176
constexpr long QKV_ELEMS = M_ * 3 * C_;            // 77,070,336
constexpr long AGENT_ELEMS = (long)B_ * AG * C_;   // 1,179,648
constexpr long S_ELEMS = (long)B_ * H_ * AG * N_;  // reused as stage-1 partial buffer
constexpr long AV_ELEMS = (long)B_ * H_ * AG * D_; // 1,179,648
constexpr long Y_ELEMS = M_ * C_;                  // 25,690,112

// stage-1 partial buffer offsets (in floats, inside g_S)
constexpr long PART_M = (long)128 * 7 * 144 * 64;  // 8,257,536
constexpr long PART_S = PART_M + 128L * 7 * 144;   // + 129,024

// ---------------- scratch (static device globals; no allocations) ----------------
__device__ float g_qkv[QKV_ELEMS];
__device__ float g_agent[AGENT_ELEMS];
__device__ float g_S[S_ELEMS];
__device__ float g_av[AV_ELEMS];
__device__ float g_y[Y_ELEMS];
__device__ float g_wr[786432];

// ================= small helpers =================
__device__ __forceinline__ uint32_t smem_u32(const void* p) {
    uint32_t a;
    asm("{ .reg .u64 t; cvta.to.shared.u64 t, %1; cvt.u32.u64 %0, t; }" : "=r"(a) : "l"(p));
    return a;
}
__device__ __forceinline__ float tf32r(float f) {
    uint32_t r;
    asm("cvt.rna.tf32.f32 %0, %1;" : "=r"(r) : "f"(f));
    return __uint_as_float(r);
}
__device__ __forceinline__ void cpa16(uint32_t dst, const float* src) {
    asm volatile("cp.async.cg.shared.global [%0], [%1], 16;" :: "r"(dst), "l"(src));
}
#define CP_COMMIT() asm volatile("cp.async.commit_group;" ::: "memory")
template<int N> __device__ __forceinline__ void cp_wait() {
    asm volatile("cp.async.wait_group %0;" :: "n"(N) : "memory");
}
__device__ __forceinline__ void mma_tf32(float* c, const uint32_t* a, const uint32_t* b) {
    asm volatile(
        "mma.sync.aligned.m16n8k8.row.col.f32.tf32.tf32.f32 "
        "{%0,%1,%2,%3}, {%4,%5,%6,%7}, {%8,%9}, {%0,%1,%2,%3};"
        : "+f"(c[0]), "+f"(c[1]), "+f"(c[2]), "+f"(c[3])
        : "r"(a[0]), "r"(a[1]), "r"(a[2]), "r"(a[3]), "r"(b[0]), "r"(b[1]));
}

// ---------------- tf32 rounding pre-pass ----------------
__global__ void round_copy(const float* __restrict__ in, float* __restrict__ out, long n4)
{
    long i = (long)blockIdx.x * blockDim.x + threadIdx.x;
    if (i >= n4) return;
    float4 v = ((const float4*)in)[i];
    v.x = tf32r(v.x); v.y = tf32r(v.y); v.z = tf32r(v.z); v.w = tf32r(v.w);
    ((float4*)out)[i] = v;
}

// ================= large tensor-core GEMM (qkv / proj) =================
constexpr int PADW = 36;
constexpr int STG  = 128 * PADW;
constexpr int GEMM_SMEM = 4 * STG * 4;   // 73,728 bytes

__global__ __launch_bounds__(256, 2)
void gemm_mma(const float* __restrict__ A, const float* __restrict__ Bw, float* __restrict__ C,
              int K, int lda, int ldb, int ldc, const float* __restrict__ bias)
{
    extern __shared__ float smem[];
    const int tid = threadIdx.x;
    const int wid = tid >> 5, lane = tid & 31;
    const int wm = wid >> 2, wn = wid & 3;
    const long m0 = (long)blockIdx.y * 128;
    const long n0 = (long)blockIdx.x * 128;

    const int r  = tid >> 3;
    const int c4 = (tid & 7) << 2;
    const uint32_t sbase = smem_u32(smem);
    const uint32_t aAddr0 = sbase + (uint32_t)((r * PADW + c4) * 4);
    const uint32_t bAddr0 = aAddr0 + (uint32_t)(STG * 4);
    const float* aSrc = A + (m0 + r) * (long)lda + c4;
    const float* bSrc = Bw + (n0 + r) * (long)ldb + c4;

    const int g = lane >> 2, t4 = lane & 3;
    const float* aF0 = smem + (wm * 64 + g) * PADW + t4;
    const float* bF0 = smem + STG + (wn * 32 + g) * PADW + t4;

    float acc[4][4][4];
#pragma unroll
    for (int i = 0; i < 4; i++)
#pragma unroll
        for (int j = 0; j < 4; j++)
#pragma unroll
            for (int l = 0; l < 4; l++) acc[i][j][l] = 0.f;

    const int nch = K / 32;

    auto issue = [&](int s, int c) {
        const uint32_t so = (uint32_t)(s * 2 * STG * 4);
        const long ko = (long)c * 32;
#pragma unroll
        for (int i = 0; i < 4; i++) {
            cpa16(aAddr0 + so + (uint32_t)(i * 32 * PADW * 4), aSrc + (long)(32 * i) * lda + ko);
            cpa16(bAddr0 + so + (uint32_t)(i * 32 * PADW * 4), bSrc + (long)(32 * i) * ldb + ko);
        }
        CP_COMMIT();
    };

    issue(0, 0);
    issue(1, 1);

    for (int c = 0; c < nch; c++) {
        if (c + 1 < nch) cp_wait<1>(); else cp_wait<0>();
        __syncthreads();

        const int s = c & 1;
        const float* Af = aF0 + s * 2 * STG;
        const float* Bf = bF0 + s * 2 * STG;
#pragma unroll
        for (int ks = 0; ks < 4; ks++) {
            uint32_t a[4][4], b[4][2];
#pragma unroll
            for (int mt = 0; mt < 4; mt++) {
                const float* p = Af + mt * 16 * PADW + ks * 8;
                a[mt][0] = __float_as_uint(p[0]);
                a[mt][1] = __float_as_uint(p[8 * PADW]);
                a[mt][2] = __float_as_uint(p[4]);
                a[mt][3] = __float_as_uint(p[8 * PADW + 4]);
            }
#pragma unroll
            for (int nt = 0; nt < 4; nt++) {
                const float* p = Bf + nt * 8 * PADW + ks * 8;
                b[nt][0] = __float_as_uint(p[0]);
                b[nt][1] = __float_as_uint(p[4]);
            }
#pragma unroll
            for (int mt = 0; mt < 4; mt++)
#pragma unroll
                for (int nt = 0; nt < 4; nt++)
                    mma_tf32(acc[mt][nt], a[mt], b[nt]);
        }
        __syncthreads();
        if (c + 2 < nch) issue(s, c + 2);
    }

    const long rowBase = m0 + wm * 64 + g;
#pragma unroll
    for (int mt = 0; mt < 4; mt++) {
        const long r0 = rowBase + mt * 16;
#pragma unroll
        for (int nt = 0; nt < 4; nt++) {
            const long col = n0 + wn * 32 + nt * 8 + t4 * 2;
            float2 v0 = make_float2(acc[mt][nt][0], acc[mt][nt][1]);
            float2 v1 = make_float2(acc[mt][nt][2], acc[mt][nt][3]);
            if (bias) {
                float2 bb = *(const float2*)&bias[col];
                v0.x += bb.x; v0.y += bb.y;
                v1.x += bb.x; v1.y += bb.y;
            }
            *(float2*)&C[r0 * (long)ldc + col] = v0;
            *(float2*)&C[(r0 + 8) * (long)ldc + col] = v1;
        }
    }
}

// ================= fused stage-1 (flash): agent attention over keys =================
// grid (7 splits, 128 z), block 288 (9 warps x m16 = 144 agent rows).
// Per split: 7 key tiles of 64 (7*7*64 = 3136). Writes unnormalized O, m, s partials.
constexpr int S1_AGP = 68, S1_KP = 68, S1_VP = 72, S1_PP = 72;
constexpr int S1_KT_OFF = 144 * S1_AGP;                 // 9792
constexpr int S1_VS_OFF = S1_KT_OFF + 64 * S1_KP;       // 14144
constexpr int S1_PS_OFF = S1_VS_OFF + 64 * S1_VP;       // 18752
constexpr int S1_SMEM = (S1_PS_OFF + 144 * S1_PP) * 4;  // 116,480 bytes

__global__ __launch_bounds__(288)
void stage1_fused(const float* __restrict__ qkv, const float* __restrict__ agent,
                  float* __restrict__ part, float scale)
{
    extern __shared__ float sm[];
    float* AgS = sm;
    float* Kt  = sm + S1_KT_OFF;
    float* Vs  = sm + S1_VS_OFF;
    float* Ps  = sm + S1_PS_OFF;

    const int z = blockIdx.y, split = blockIdx.x;
    const int b = z >> 3, h = z & 7;
    const int tid = threadIdx.x, wid = tid >> 5, lane = tid & 31;
    const int g = lane >> 2, t4 = lane & 3;

    const float* Agz = agent + (long)b * AG * C_ + h * 64;
    const float* Kz  = qkv + (long)b * N_ * 1536 + 512 + h * 64;
    const float* Vz  = qkv + (long)b * N_ * 1536 + 1024 + h * 64;

    // load agent tile [144 x 64] (tf32r) — once
    for (int i = tid; i < 144 * 16; i += 288) {
        int row = i >> 4, c4 = (i & 15) << 2;
        float4 v = *(const float4*)(Agz + (long)row * C_ + c4);
        v.x = tf32r(v.x); v.y = tf32r(v.y); v.z = tf32r(v.z); v.w = tf32r(v.w);
        *(float4*)&AgS[row * S1_AGP + c4] = v;
    }
    __syncthreads();

    const int r = wid * 16 + g;   // agent row (0..143)

    // preload A fragments for logits (reused every tile)
    uint32_t afr[8][4];
#pragma unroll
    for (int ks = 0; ks < 8; ks++) {
        const float* p = &AgS[r * S1_AGP + ks * 8 + t4];
        afr[ks][0] = __float_as_uint(p[0]);
        afr[ks][1] = __float_as_uint(p[8 * S1_AGP]);
        afr[ks][2] = __float_as_uint(p[4]);
        afr[ks][3] = __float_as_uint(p[8 * S1_AGP + 4]);
    }

    float m0r = -3.4e38f, m1r = -3.4e38f, s0 = 0.f, s1 = 0.f;
    float O[8][4];
#pragma unroll
    for (int nt = 0; nt < 8; nt++)
#pragma unroll
        for (int l = 0; l < 4; l++) O[nt][l] = 0.f;

    int k0 = split * 448;
    for (int t = 0; t < 7; t++, k0 += 64) {
        __syncthreads();   // previous tile's Kt/Vs reads done
        // load K,V tile [64 x 64] each (tf32r)
        for (int i = tid; i < 64 * 16; i += 288) {
            int row = i >> 4, c4 = (i & 15) << 2;
            float4 kv = *(const float4*)(Kz + (long)(k0 + row) * 1536 + c4);
            kv.x = tf32r(kv.x); kv.y = tf32r(kv.y); kv.z = tf32r(kv.z); kv.w = tf32r(kv.w);
            *(float4*)&Kt[row * S1_KP + c4] = kv;
            float4 vv = *(const float4*)(Vz + (long)(k0 + row) * 1536 + c4);
            vv.x = tf32r(vv.x); vv.y = tf32r(vv.y); vv.z = tf32r(vv.z); vv.w = tf32r(vv.w);
            *(float4*)&Vs[row * S1_VP + c4] = vv;
        }
        __syncthreads();

        // logits L[16 agent rows x 64 keys] per warp
        float L[8][4];
#pragma unroll
        for (int nt = 0; nt < 8; nt++)
#pragma unroll
            for (int l = 0; l < 4; l++) L[nt][l] = 0.f;
#pragma unroll
        for (int ks = 0; ks < 8; ks++) {
#pragma unroll
            for (int nt = 0; nt < 8; nt++) {
                uint32_t bb[2];
                const float* p = &Kt[(nt * 8 + g) * S1_KP + ks * 8 + t4];
                bb[0] = __float_as_uint(p[0]);
                bb[1] = __float_as_uint(p[4]);
                mma_tf32(L[nt], afr[ks], bb);
            }
        }

        // online softmax over keys (rows r and r+8; row spread over quad)
        float lm0 = -3.4e38f, lm1 = -3.4e38f;
#pragma unroll
        for (int nt = 0; nt < 8; nt++) {
            lm0 = fmaxf(lm0, fmaxf(L[nt][0], L[nt][1]));
            lm1 = fmaxf(lm1, fmaxf(L[nt][2], L[nt][3]));
        }
        lm0 *= scale; lm1 *= scale;
#pragma unroll
        for (int o = 1; o < 4; o <<= 1) {
            lm0 = fmaxf(lm0, __shfl_xor_sync(0xffffffffu, lm0, o));
            lm1 = fmaxf(lm1, __shfl_xor_sync(0xffffffffu, lm1, o));
        }
        float nm0 = fmaxf(m0r, lm0), nm1 = fmaxf(m1r, lm1);
        float al0 = __expf(m0r - nm0), al1 = __expf(m1r - nm1);
        s0 *= al0; s1 *= al1;
#pragma unroll
        for (int nt = 0; nt < 8; nt++) {
            O[nt][0] *= al0; O[nt][1] *= al0; O[nt][2] *= al1; O[nt][3] *= al1;
            float p0 = __expf(L[nt][0] * scale - nm0); s0 += p0;
            float p1 = __expf(L[nt][1] * scale - nm0); s0 += p1;
            float p2 = __expf(L[nt][2] * scale - nm1); s1 += p2;
            float p3 = __expf(L[nt][3] * scale - nm1); s1 += p3;
            int col = nt * 8 + 2 * t4;
            Ps[r * S1_PP + col]           = tf32r(p0);
            Ps[r * S1_PP + col + 1]       = tf32r(p1);
            Ps[(r + 8) * S1_PP + col]     = tf32r(p2);
            Ps[(r + 8) * S1_PP + col + 1] = tf32r(p3);
        }
        m0r = nm0; m1r = nm1;
        // warp reads only its own Ps rows -> no block sync needed

        // O += P(16x64) @ V(64x64)
#pragma unroll
        for (int ks = 0; ks < 8; ks++) {
            uint32_t a2[4];
            const float* p = &Ps[r * S1_PP + ks * 8 + t4];
            a2[0] = __float_as_uint(p[0]);
            a2[1] = __float_as_uint(p[8 * S1_PP]);
            a2[2] = __float_as_uint(p[4]);
            a2[3] = __float_as_uint(p[8 * S1_PP + 4]);
#pragma unroll
            for (int nt = 0; nt < 8; nt++) {
                uint32_t bb[2];
                bb[0] = __float_as_uint(Vs[(ks * 8 + t4) * S1_VP + nt * 8 + g]);
                bb[1] = __float_as_uint(Vs[(ks * 8 + t4 + 4) * S1_VP + nt * 8 + g]);
                mma_tf32(O[nt], a2, bb);
            }
        }
    }

    // finalize row sums across quad
#pragma unroll
    for (int o = 1; o < 4; o <<= 1) {
        s0 += __shfl_xor_sync(0xffffffffu, s0, o);
        s1 += __shfl_xor_sync(0xffffffffu, s1, o);
    }

    // write partials
    const long pb = ((long)z * 7 + split) * 144;
#pragma unroll
    for (int nt = 0; nt < 8; nt++) {
        int col = nt * 8 + 2 * t4;
        *(float2*)&part[(pb + r) * 64 + col]     = make_float2(O[nt][0], O[nt][1]);
        *(float2*)&part[(pb + r + 8) * 64 + col] = make_float2(O[nt][2], O[nt][3]);
    }
    if (t4 == 0) {
        part[PART_M + pb + r]     = m0r;  part[PART_S + pb + r]     = s0;
        part[PART_M + pb + r + 8] = m1r;  part[PART_S + pb + r + 8] = s1;
    }
}

// merge 7 split partials -> agent_v
__global__ void stage1_merge(const float* __restrict__ part, float* __restrict__ av)
{
    long i = (long)blockIdx.x * 256 + threadIdx.x;     // 128*144*16
    if (i >= (long)128 * 144 * 16) return;
    int d4 = (int)(i & 15);
    long t = i >> 4;
    int p = (int)(t % 144);
    int z = (int)(t / 144);
    long base = (long)z * 7 * 144 + p;

    float M = -3.4e38f;
#pragma unroll
    for (int sp = 0; sp < 7; sp++)
        M = fmaxf(M, part[PART_M + base + sp * 144]);
    float den = 0.f;
    float4 acc = make_float4(0.f, 0.f, 0.f, 0.f);
#pragma unroll
    for (int sp = 0; sp < 7; sp++) {
        float w = __expf(part[PART_M + base + sp * 144] - M);
        den += w * part[PART_S + base + sp * 144];
        float4 o = *(const float4*)&part[(base + sp * 144) * 64 + d4 * 4];
        acc.x += w * o.x; acc.y += w * o.y; acc.z += w * o.z; acc.w += w * o.w;
    }
    float inv = 1.f / den;
    acc.x *= inv; acc.y *= inv; acc.z *= inv; acc.w *= inv;
    *(float4*)&av[((long)z * 144 + p) * 64 + d4 * 4] = acc;
}

// ================= fused stage-2 + depthwise conv =================
constexpr int S2_AP = 68, S2_BP = 68, S2_PP = 148, S2_VP = 72;
constexpr int S2_VS_OFF = 128 * S2_PP;                    // 18944 floats
constexpr int S2_W_OFF  = S2_VS_OFF + AG * S2_VP;         // 29312
constexpr int S2_SMEM = (S2_W_OFF + 576 + 64) * 4;        // 119,808 bytes

__global__ __launch_bounds__(256)
void stage2_fused(const float* __restrict__ Q, const float* __restrict__ Ag,
                  const float* __restrict__ Av, float* __restrict__ Y,
                  const float* __restrict__ dwcW, const float* __restrict__ dwcB,
                  float scale)
{
    extern __shared__ float sm[];
    float* As = sm;                    // [128][68] (aliases Ps)
    float* Bs = sm + 128 * S2_AP;      // [144][68] (aliases Ps)
    float* Ps = sm;                    // [128][148]
    float* Vs = sm + S2_VS_OFF;        // [144][72]
    float* Ws = sm + S2_W_OFF;         // [64*9]
    float* Bb = sm + S2_W_OFF + 576;   // [64]

    const int z = blockIdx.y;
    const int b = z >> 3, h = z & 7;
    const float* Qz  = Q + (long)b * N_ * 1536 + h * 64;
    const float* Agz = Ag + (long)b * AG * C_ + h * 64;
    const float* Avz = Av + (long)z * AG * 64;
    const float* vb  = Q + (long)b * N_ * 1536 + 1024 + h * 64;   // v for dwc
    float* Yz = Y + (long)b * N_ * C_ + h * 64;

    const int tid = threadIdx.x;
    const int wid = tid >> 5, lane = tid & 31;
    const int g = lane >> 2, t4 = lane & 3;
    const int m0 = blockIdx.x * 128;

    // ---- load Q tile [128 x 64] ----
#pragma unroll
    for (int i = 0; i < 8; i++) {
        int idx = tid + i * 256;
        int row = idx >> 4, c4 = (idx & 15) << 2;
        float4 v = make_float4(0.f, 0.f, 0.f, 0.f);
        if (m0 + row < N_)
            v = *(const float4*)(Qz + (long)(m0 + row) * 1536 + c4);
        v.x = tf32r(v.x); v.y = tf32r(v.y); v.z = tf32r(v.z); v.w = tf32r(v.w);
        *(float4*)&As[row * S2_AP + c4] = v;
    }
    // ---- load agent tile [144 x 64] ----
#pragma unroll
    for (int i = 0; i < 9; i++) {
        int idx = tid + i * 256;
        int row = idx >> 4, c4 = (idx & 15) << 2;
        float4 v = *(const float4*)(Agz + (long)row * C_ + c4);
        v.x = tf32r(v.x); v.y = tf32r(v.y); v.z = tf32r(v.z); v.w = tf32r(v.w);
        *(float4*)&Bs[row * S2_BP + c4] = v;
    }
    // ---- load agent_v [144 x 64] ----
#pragma unroll
    for (int i = 0; i < 9; i++) {
        int idx = tid + i * 256;
        int row = idx >> 4, c4 = (idx & 15) << 2;
        float4 v = *(const float4*)(Avz + (long)row * 64 + c4);
        v.x = tf32r(v.x); v.y = tf32r(v.y); v.z = tf32r(v.z); v.w = tf32r(v.w);
        *(float4*)&Vs[row * S2_VP + c4] = v;
    }
    // ---- load dwc weights/bias for this head's 64 channels ----
    for (int i = tid; i < 640; i += 256) {
        if (i < 576) Ws[i] = dwcW[h * 576 + i];
        else         Bb[i - 576] = dwcB[h * 64 + i - 576];
    }
    __syncthreads();

    // ---- phase 1: logits L[128 x 144] ----
    const int r = wid * 16 + g;
    float accL[18][4];
#pragma unroll
    for (int nt = 0; nt < 18; nt++)
#pragma unroll
        for (int l = 0; l < 4; l++) accL[nt][l] = 0.f;

#pragma unroll
    for (int ks = 0; ks < 8; ks++) {
        uint32_t a[4];
        {
            const float* p = &As[r * S2_AP + ks * 8 + t4];
            a[0] = __float_as_uint(p[0]);
            a[1] = __float_as_uint(p[8 * S2_AP]);
            a[2] = __float_as_uint(p[4]);
            a[3] = __float_as_uint(p[8 * S2_AP + 4]);
        }
#pragma unroll
        for (int nt = 0; nt < 18; nt++) {
            uint32_t bfr[2];
            const float* p = &Bs[(nt * 8 + g) * S2_BP + ks * 8 + t4];
            bfr[0] = __float_as_uint(p[0]);
            bfr[1] = __float_as_uint(p[4]);
            mma_tf32(accL[nt], a, bfr);
        }
    }

    // ---- softmax over 144 ----
    float m0r = -3.4e38f, m1r = -3.4e38f;
#pragma unroll
    for (int nt = 0; nt < 18; nt++) {
        m0r = fmaxf(m0r, fmaxf(accL[nt][0], accL[nt][1]));
        m1r = fmaxf(m1r, fmaxf(accL[nt][2], accL[nt][3]));
    }
    m0r *= scale; m1r *= scale;
#pragma unroll
    for (int o = 1; o < 4; o <<= 1) {
        m0r = fmaxf(m0r, __shfl_xor_sync(0xffffffffu, m0r, o));
        m1r = fmaxf(m1r, __shfl_xor_sync(0xffffffffu, m1r, o));
    }
    float s0 = 0.f, s1 = 0.f;
#pragma unroll
    for (int nt = 0; nt < 18; nt++) {
        accL[nt][0] = __expf(accL[nt][0] * scale - m0r); s0 += accL[nt][0];
        accL[nt][1] = __expf(accL[nt][1] * scale - m0r); s0 += accL[nt][1];
        accL[nt][2] = __expf(accL[nt][2] * scale - m1r); s1 += accL[nt][2];
        accL[nt][3] = __expf(accL[nt][3] * scale - m1r); s1 += accL[nt][3];
    }
#pragma unroll
    for (int o = 1; o < 4; o <<= 1) {
        s0 += __shfl_xor_sync(0xffffffffu, s0, o);
        s1 += __shfl_xor_sync(0xffffffffu, s1, o);
    }
    const float inv0 = 1.0f / s0, inv1 = 1.0f / s1;

    __syncthreads();   // As/Bs reads done before Ps overwrite

#pragma unroll
    for (int nt = 0; nt < 18; nt++) {
        const int col = nt * 8 + 2 * t4;
        Ps[r * S2_PP + col]           = tf32r(accL[nt][0] * inv0);
        Ps[r * S2_PP + col + 1]       = tf32r(accL[nt][1] * inv0);
        Ps[(r + 8) * S2_PP + col]     = tf32r(accL[nt][2] * inv1);
        Ps[(r + 8) * S2_PP + col + 1] = tf32r(accL[nt][3] * inv1);
    }
    __syncthreads();

    // ---- phase 3: out = P @ agent_v  [128 x 64] ----
    float acc2[8][4];
#pragma unroll
    for (int nt = 0; nt < 8; nt++)
#pragma unroll
        for (int l = 0; l < 4; l++) acc2[nt][l] = 0.f;

#pragma unroll
    for (int ks = 0; ks < 18; ks++) {
        uint32_t a[4];
        {
            const float* p = &Ps[r * S2_PP + ks * 8 + t4];
            a[0] = __float_as_uint(p[0]);
            a[1] = __float_as_uint(p[8 * S2_PP]);
            a[2] = __float_as_uint(p[4]);
            a[3] = __float_as_uint(p[8 * S2_PP + 4]);
        }
#pragma unroll
        for (int nt = 0; nt < 8; nt++) {
            uint32_t bfr[2];
            bfr[0] = __float_as_uint(Vs[(ks * 8 + t4) * S2_VP + nt * 8 + g]);
            bfr[1] = __float_as_uint(Vs[(ks * 8 + t4 + 4) * S2_VP + nt * 8 + g]);
            mma_tf32(acc2[nt], a, bfr);
        }
    }

    // ---- epilogue: + depthwise 3x3 conv + bias, tf32-rounded ----
    const int gr = m0 + r;
#pragma unroll
    for (int rr = 0; rr < 2; rr++) {
        const int l = gr + rr * 8;
        if (l >= N_) continue;
        const int hh = l / 56, ww = l - hh * 56;
        float add[16];
#pragma unroll
        for (int nt = 0; nt < 8; nt++) {
            int c0 = nt * 8 + 2 * t4;
            add[nt * 2]     = Bb[c0];
            add[nt * 2 + 1] = Bb[c0 + 1];
        }
#pragma unroll
        for (int kh = 0; kh < 3; kh++) {
            int h2 = hh + kh - 1;
            if (h2 < 0 || h2 >= 56) continue;
#pragma unroll
            for (int kw = 0; kw < 3; kw++) {
                int w2 = ww + kw - 1;
                if (w2 < 0 || w2 >= 56) continue;
                const float* vrow = vb + (long)(h2 * 56 + w2) * 1536;
                const int j = kh * 3 + kw;
#pragma unroll
                for (int nt = 0; nt < 8; nt++) {
                    int c0 = nt * 8 + 2 * t4;
                    float2 vv = *(const float2*)&vrow[c0];
                    add[nt * 2]     = fmaf(vv.x, Ws[c0 * 9 + j],       add[nt * 2]);
                    add[nt * 2 + 1] = fmaf(vv.y, Ws[(c0 + 1) * 9 + j], add[nt * 2 + 1]);
                }
            }
        }
#pragma unroll
        for (int nt = 0; nt < 8; nt++) {
            const int col = nt * 8 + 2 * t4;
            float2 v;
            v.x = tf32r(acc2[nt][rr * 2]     + add[nt * 2]);
            v.y = tf32r(acc2[nt][rr * 2 + 1] + add[nt * 2 + 1]);
            *(float2*)&Yz[(long)l * C_ + col] = v;
        }
    }
}

// ---------------- adaptive avg pool of q -> agent tokens ----------------
__global__ void pool_kernel(const float* __restrict__ qkv, float* __restrict__ agent)
{
    int b = blockIdx.x;
    int pq = blockIdx.y;
    int p = pq / POOL, q = pq % POOL;
    int ch = threadIdx.x;
    int hs = (p * HH) / POOL, he = ((p + 1) * HH + POOL - 1) / POOL;
    int ws = (q * HH) / POOL, we = ((q + 1) * HH + POOL - 1) / POOL;
    float inv = 1.0f / (float)((he - hs) * (we - ws));
    const float* base = qkv + (long)b * N_ * 1536;
    float s = 0.f;
    for (int h = hs; h < he; h++)
        for (int w = ws; w < we; w++)
            s += base[(long)(h * HH + w) * 1536 + ch];
    agent[((long)b * AG + pq) * C_ + ch] = s * inv;
}

// ---------------- launch ----------------
extern "C" void kernel_launch(void* const* d_in, const int* in_sizes, int n_in,
                              void* d_out, int out_size)
{
    const float* x      = (const float*)d_in[0];
    const float* qkv_w  = (const float*)d_in[1];
    const float* proj_w = (const float*)d_in[2];
    const float* proj_b = (const float*)d_in[3];
    const float* dwc_w  = (const float*)d_in[4];
    const float* dwc_b  = (const float*)d_in[5];
    float* out = (float*)d_out;

    float *qkv, *agent, *S, *av, *y, *wr;
    cudaGetSymbolAddress((void**)&qkv,   g_qkv);
    cudaGetSymbolAddress((void**)&agent, g_agent);
    cudaGetSymbolAddress((void**)&S,     g_S);
    cudaGetSymbolAddress((void**)&av,    g_av);
    cudaGetSymbolAddress((void**)&y,     g_y);
    cudaGetSymbolAddress((void**)&wr,    g_wr);

    cudaFuncSetAttribute(gemm_mma, cudaFuncAttributeMaxDynamicSharedMemorySize, GEMM_SMEM);
    cudaFuncSetAttribute(stage1_fused, cudaFuncAttributeMaxDynamicSharedMemorySize, S1_SMEM);
    cudaFuncSetAttribute(stage2_fused, cudaFuncAttributeMaxDynamicSharedMemorySize, S2_SMEM);

    const float scale = 0.125f;

    // 0) tf32-round x (into y scratch) and qkv_w
    {
        long n4 = Y_ELEMS / 4;
        round_copy<<<(int)((n4 + 255) / 256), 256>>>(x, y, n4);
        long w4 = 786432 / 4;
        round_copy<<<(int)((w4 + 255) / 256), 256>>>(qkv_w, wr, w4);
    }

    // 1) qkv = x @ qkv_w^T
    gemm_mma<<<dim3(12, 392), 256, GEMM_SMEM>>>(y, wr, qkv, 512, 512, 512, 1536, nullptr);

    // 2) agent tokens
    pool_kernel<<<dim3(B_, AG), 512>>>(qkv, agent);

    // 3+4+5) fused flash stage-1 -> partials -> merge into agent_v
    stage1_fused<<<dim3(7, 128), 288, S1_SMEM>>>(qkv, agent, S, scale);
    stage1_merge<<<1152, 256>>>(S, av);

    // 6+7+8+9) fused: y = tf32r( softmax(scale*qh@agent^T) @ agent_v + dwc(v) + dwc_b )
    stage2_fused<<<dim3(25, 128), 256, S2_SMEM>>>(qkv, agent, av, y, dwc_w, dwc_b, scale);

    // 9.5) tf32-round proj_w
    {
        long w4 = 262144 / 4;
        round_copy<<<(int)((w4 + 255) / 256), 256>>>(proj_w, wr, w4);
    }

    // 10) out = y @ proj_w^T + proj_b
    gemm_mma<<<dim3(4, 392), 256, GEMM_SMEM>>>(y, wr, out, 512, 512, 512, 512, proj_b);
}